// round 5
// baseline (speedup 1.0000x reference)
#include <cuda_runtime.h>
#include <cstdint>
#include <math.h>

#define SEQ 256
#define NB 64
#define HID 300
#define G4 1200
#define NTAG 12

// recurrence: 2 dirs x 8 batch-groups x 8 unit-slices = 128 CTAs, clusters of 8
#define RBG 8           // batch groups
#define RUS 8           // unit slices (= cluster size)
#define RBS 8           // batch per group
#define RUPC 38         // units per slice (last slice has 34)
#define R_P 76          // row pairs (152 gate rows / 2)
#define R_KCH 75
#define R_THREADS 320   // 304 active = 4 ksplit x 76 rowpairs

// input-projection config: 20 CTAs of 60 gate rows cover the 1200 rows
#define IP_MB 20
#define IP_ROWS 60
#define IP_THREADS 320

// smem float offsets for k_recur
#define OFF_WS   0
#define OFF_HS0  45600
#define OFF_HS1  48000
#define OFF_RED  50400
#define R_SMEMF  55264   // total floats (221056 bytes)

typedef unsigned long long ull;

__device__ __forceinline__ ull pack2(float lo, float hi) {
    ull r; asm("mov.b64 %0, {%1, %2};" : "=l"(r) : "f"(lo), "f"(hi)); return r;
}
__device__ __forceinline__ void unpack2(ull v, float& lo, float& hi) {
    asm("mov.b64 {%0, %1}, %2;" : "=f"(lo), "=f"(hi) : "l"(v));
}
__device__ __forceinline__ ull fma2(ull a, ull b, ull c) {
    ull d; asm("fma.rn.f32x2 %0, %1, %2, %3;" : "=l"(d) : "l"(a), "l"(b), "l"(c)); return d;
}
__device__ __forceinline__ ull add2(ull a, ull b) {
    ull d; asm("add.rn.f32x2 %0, %1, %2;" : "=l"(d) : "l"(a), "l"(b)); return d;
}
__device__ __forceinline__ float ftanh(float x) {
    float y; asm("tanh.approx.f32 %0, %1;" : "=f"(y) : "f"(x)); return y;
}
__device__ __forceinline__ float fsigm(float x) {
    return 0.5f * ftanh(0.5f * x) + 0.5f;
}
__device__ __forceinline__ void st_cluster64(uint32_t addr, int rank, ull v) {
    uint32_t ra;
    asm volatile("mapa.shared::cluster.u32 %0, %1, %2;" : "=r"(ra) : "r"(addr), "r"(rank));
    asm volatile("st.shared::cluster.b64 [%0], %1;" :: "r"(ra), "l"(v) : "memory");
}

// ---------------- scratch (device globals; no allocations) ----------------
__device__ float g_XT[SEQ * HID * NB];             // x transposed: [s][k][b]
__device__ float g_G[2][SEQ][G4 * NB];             // input proj + bias: [d][s][row][b]
__device__ float g_hall[2][SEQ][RBG * HID * RBS];  // h: [d][s][group][u*8+bo]
__device__ float g_emit[SEQ][NB][NTAG];            // emissions

extern __shared__ float sm[];

// ---------------- embedding gather + transpose ----------------
__global__ void k_gather(const int* __restrict__ sent, const float* __restrict__ emb) {
    int s = blockIdx.x;
    __shared__ float sx[64][33];
    __shared__ int rows[64];
    int t = threadIdx.x;  // 256
    if (t < 64) rows[t] = sent[t * SEQ + s];
    __syncthreads();
    for (int kc = 0; kc < 10; kc++) {
        int kbase = kc * 32;
        int width = HID - kbase; if (width > 32) width = 32;
        int kk = t & 31, bg = t >> 5;
        if (kk < width) {
            for (int b = bg; b < 64; b += 8)
                sx[b][kk] = emb[rows[b] * HID + kbase + kk];
        }
        __syncthreads();
        int b = t & 63, kg = t >> 6;
        for (int k2 = kg; k2 < width; k2 += 4)
            g_XT[(s * HID + kbase + k2) * NB + b] = sx[b][k2];
        __syncthreads();
    }
}

// ---------------- input projection GEMM: G[d][s][row][b] = W_ih @ x + bias ----------------
__global__ void __launch_bounds__(IP_THREADS, 1) k_inproj(
    const float* __restrict__ Wf, const float* __restrict__ bf,
    const float* __restrict__ Wb, const float* __restrict__ bb)
{
    int m = blockIdx.x, s = blockIdx.y, d = blockIdx.z;
    const float* W    = d ? Wb : Wf;
    const float* bias = d ? bb : bf;
    float* xs  = sm;               // 19200 floats
    float* ws  = sm + HID * NB;    // 18000 floats: ws[k*60 + r]
    int t = threadIdx.x;
    int u0 = m * 15;

    for (int idx = t; idx < HID * IP_ROWS; idx += IP_THREADS) {
        int k = idx / IP_ROWS, r = idx - k * IP_ROWS;
        int ul = r >> 2, gate = r & 3;
        ws[idx] = W[(gate * HID + u0 + ul) * HID + k];
    }
    {
        const float4* src = (const float4*)(g_XT + s * HID * NB);
        float4* dst = (float4*)xs;
        for (int idx = t; idx < HID * NB / 4; idx += IP_THREADS) dst[idx] = src[idx];
    }
    __syncthreads();

    int b = t & 63, rg = t >> 6;   // rg 0..4, owns rows rg*12 .. rg*12+11
    ull acc[6];
#pragma unroll
    for (int p = 0; p < 6; p++) acc[p] = 0ull;

    const ulonglong2* wp = ((const ulonglong2*)ws) + rg * 3;
    const float* xp = xs + b;
#pragma unroll 4
    for (int k = 0; k < HID; k++) {
        float hv = xp[k * NB];
        ull h2 = pack2(hv, hv);
        ulonglong2 w0 = wp[0], w1 = wp[1], w2 = wp[2];
        acc[0] = fma2(w0.x, h2, acc[0]);
        acc[1] = fma2(w0.y, h2, acc[1]);
        acc[2] = fma2(w1.x, h2, acc[2]);
        acc[3] = fma2(w1.y, h2, acc[3]);
        acc[4] = fma2(w2.x, h2, acc[4]);
        acc[5] = fma2(w2.y, h2, acc[5]);
        wp += 15;
    }

    float* Gd = g_G[d][s];
#pragma unroll
    for (int p = 0; p < 6; p++) {
        float v0, v1; unpack2(acc[p], v0, v1);
        int r0 = rg * 12 + 2 * p, r1 = r0 + 1;
        int row0 = (r0 & 3) * HID + u0 + (r0 >> 2);
        int row1 = (r1 & 3) * HID + u0 + (r1 >> 2);
        Gd[row0 * NB + b] = v0 + bias[row0];
        Gd[row1 * NB + b] = v1 + bias[row1];
    }
}

// ---------------- persistent LSTM recurrence: 8-CTA clusters, DSMEM h exchange ----------------
// Cluster = (d, g): 8 CTAs, each owns 38 units x 8 batches. h exchanged via st.shared::cluster
// into double-buffered smem; one split cluster barrier per step. No global traffic for h.
__global__ void __launch_bounds__(R_THREADS, 1) __cluster_dims__(RUS, 1, 1)
k_recur(const float* __restrict__ Whf, const float* __restrict__ Whb)
{
    int bid = blockIdx.x;
    int d = bid >> 6;
    int g = (bid >> 3) & 7;
    int m = bid & 7;            // rank within cluster = unit slice
    const float* W = d ? Whb : Whf;

    float* ws = sm + OFF_WS;           // ws[k*152 + r], r = ul*4+gate (row pairs packed)
    ull*  red = (ull*)(sm + OFF_RED);

    uint32_t smem_u32;
    asm("{ .reg .u64 t0; cvta.to.shared.u64 t0, %1; cvt.u32.u64 %0, t0; }"
        : "=r"(smem_u32) : "l"(sm));
    uint32_t hs0_u32 = smem_u32 + OFF_HS0 * 4;
    uint32_t hs1_u32 = smem_u32 + OFF_HS1 * 4;

    int t = threadIdx.x;
    int u0 = m * RUPC;
    int cu = HID - u0; if (cu > RUPC) cu = RUPC;

    // stage weights (zero-padded beyond cu)
    for (int idx = t; idx < HID * 152; idx += R_THREADS) {
        int k = idx / 152, r = idx - k * 152;
        int ul = r >> 2, gate = r & 3;
        ws[idx] = (ul < cu) ? W[(gate * HID + u0 + ul) * HID + k] : 0.f;
    }
    __syncthreads();

    int ks = t / R_P;          // 0..3 active, 4 = spare
    int p  = t - ks * R_P;     // rowpair 0..75
    int k0 = (ks & 3) * R_KCH;
    int bp = (ks > 3) ? 3 : ks;        // batch-pair
    int ul = p >> 1;
    bool doer = (t < 304) && ((p & 1) == 0) && (ul < cu);
    int boff = g * RBS + bp * 2;
    uint32_t my_hoff = ((u0 + ul) * RBS + bp * 2) * 4;   // byte offset in hs buffer
    float c0 = 0.f, c1 = 0.f;
    const ull* wsu = (const ull*)ws;

    for (int step = 0; step < SEQ; step++) {
        int pos = d ? (SEQ - 1 - step) : step;
        const float* Gp = g_G[d][pos];

        // prefetch this step's G (hidden under the cluster wait)
        float2 Gv0, Gv1, Gv2, Gv3;
        if (doer) {
            int gb = (u0 + ul) * NB + boff;
            Gv0 = *(const float2*)(Gp + 0 * HID * NB + gb);
            Gv1 = *(const float2*)(Gp + 1 * HID * NB + gb);
            Gv2 = *(const float2*)(Gp + 2 * HID * NB + gb);
            Gv3 = *(const float2*)(Gp + 3 * HID * NB + gb);
        }

        float s0lo = 0.f, s0hi = 0.f, s1lo = 0.f, s1hi = 0.f;

        if (step > 0) {
            // wait for previous step's arrive: peers' h writes now visible
            asm volatile("barrier.cluster.wait.aligned;" ::: "memory");

            const ulonglong2* hsu =
                (const ulonglong2*)(sm + ((step & 1) ? OFF_HS1 : OFF_HS0));

            // partial GEMV: 2 rows x 8 batches per thread over 75 k's
            ull a00 = 0, a01 = 0, a02 = 0, a03 = 0;
            ull a10 = 0, a11 = 0, a12 = 0, a13 = 0;
#pragma unroll 5
            for (int kk = 0; kk < R_KCH; kk++) {
                int k = k0 + kk;
                ull w = wsu[k * R_P + p];
                float w0, w1; unpack2(w, w0, w1);
                ull w00 = pack2(w0, w0), w11 = pack2(w1, w1);
                ulonglong2 hA = hsu[k * 2];
                ulonglong2 hB = hsu[k * 2 + 1];
                a00 = fma2(w00, hA.x, a00); a01 = fma2(w00, hA.y, a01);
                a02 = fma2(w00, hB.x, a02); a03 = fma2(w00, hB.y, a03);
                a10 = fma2(w11, hA.x, a10); a11 = fma2(w11, hA.y, a11);
                a12 = fma2(w11, hB.x, a12); a13 = fma2(w11, hB.y, a13);
            }
            if (t < 304) {
                int base = p * 32 + ks;
                red[base + 0 * 8 + 0] = a00; red[base + 1 * 8 + 0] = a01;
                red[base + 2 * 8 + 0] = a02; red[base + 3 * 8 + 0] = a03;
                red[base + 0 * 8 + 4] = a10; red[base + 1 * 8 + 4] = a11;
                red[base + 2 * 8 + 4] = a12; red[base + 3 * 8 + 4] = a13;
            }
            __syncthreads();

            // phase2: thread (p, bp) sums 4 k-splits for rows 2p,2p+1 (2 batches)
            {
                const ulonglong2* r2 = (const ulonglong2*)red;
                int ib = (p * 8 + bp * 2) * 2;
                ulonglong2 q0 = r2[ib + 0], q1 = r2[ib + 1];
                ulonglong2 q2 = r2[ib + 2], q3 = r2[ib + 3];
                ull s0 = add2(add2(q0.x, q0.y), add2(q1.x, q1.y));
                ull s1 = add2(add2(q2.x, q2.y), add2(q3.x, q3.y));
                unpack2(s0, s0lo, s0hi);
                unpack2(s1, s1lo, s1hi);
            }
        }

        // exchange: even-p thread (gates i,f) pulls gates g,o from odd partner (t+1)
        float g2lo = __shfl_down_sync(0xffffffffu, s0lo, 1);
        float g2hi = __shfl_down_sync(0xffffffffu, s0hi, 1);
        float g3lo = __shfl_down_sync(0xffffffffu, s1lo, 1);
        float g3hi = __shfl_down_sync(0xffffffffu, s1hi, 1);

        if (doer) {
            float i0 = fsigm(s0lo + Gv0.x), i1 = fsigm(s0hi + Gv0.y);
            float f0 = fsigm(s1lo + Gv1.x), f1 = fsigm(s1hi + Gv1.y);
            float q0 = ftanh(g2lo + Gv2.x), q1 = ftanh(g2hi + Gv2.y);
            float o0 = fsigm(g3lo + Gv3.x), o1 = fsigm(g3hi + Gv3.y);
            c0 = f0 * c0 + i0 * q0;
            c1 = f1 * c1 + i1 * q1;
            float h0 = o0 * ftanh(c0);
            float h1 = o1 * ftanh(c1);
            ull hv = pack2(h0, h1);

            // push h into all 8 cluster CTAs' write buffer
            uint32_t wbuf = ((step & 1) ? hs0_u32 : hs1_u32) + my_hoff;
#pragma unroll
            for (int r = 0; r < RUS; r++) st_cluster64(wbuf, r, hv);

            // global copy for k_emit (off critical path)
            float2 hg; hg.x = h0; hg.y = h1;
            *(float2*)(g_hall[d][pos] + g * (HID * RBS) + (u0 + ul) * RBS + bp * 2) = hg;
        }

        // signal completion of this step (matched by wait at top of next step)
        asm volatile("barrier.cluster.arrive.aligned;" ::: "memory");
    }
    // balance the final arrive
    asm volatile("barrier.cluster.wait.aligned;" ::: "memory");
}

// ---------------- emissions: emit[s][b][j] = W_lin @ [h_f; h_b] + b_lin ----------------
__global__ void k_emit(const float* __restrict__ Wl, const float* __restrict__ bl) {
    int s = blockIdx.x, t = threadIdx.x;  // 256
    __shared__ float wl[600 * NTAG];
    __shared__ float red2[4 * NTAG * NB];
    for (int idx = t; idx < 600 * NTAG; idx += 256) {
        int k = idx / NTAG, j = idx - k * NTAG;
        wl[idx] = Wl[j * 600 + k];
    }
    __syncthreads();
    int b = t & 63, ksx = t >> 6;
    int gof = (b >> 3) * (HID * RBS) + (b & 7);
    float acc[NTAG];
#pragma unroll
    for (int j = 0; j < NTAG; j++) acc[j] = 0.f;
    const float* hf = g_hall[0][s];
    const float* hb = g_hall[1][s];
    int k0 = ksx * 150;
    for (int k = k0; k < k0 + 150; k++) {
        float v = (k < HID) ? hf[gof + k * RBS] : hb[gof + (k - HID) * RBS];
        const float4* w4 = (const float4*)(wl + k * NTAG);
#pragma unroll
        for (int q = 0; q < 3; q++) {
            float4 w = w4[q];
            acc[4 * q + 0] += w.x * v; acc[4 * q + 1] += w.y * v;
            acc[4 * q + 2] += w.z * v; acc[4 * q + 3] += w.w * v;
        }
    }
#pragma unroll
    for (int j = 0; j < NTAG; j++) red2[(ksx * NTAG + j) * NB + b] = acc[j];
    __syncthreads();
    for (int idx = t; idx < NTAG * NB; idx += 256) {
        int j = idx >> 6, b2 = idx & 63;
        float v = red2[(0 * NTAG + j) * NB + b2] + red2[(1 * NTAG + j) * NB + b2]
                + red2[(2 * NTAG + j) * NB + b2] + red2[(3 * NTAG + j) * NB + b2];
        g_emit[s][b2][j] = v + bl[j];
    }
}

// ---------------- CRF forward + gold score + loss (one warp per batch) ----------------
__global__ void k_crf(const int* __restrict__ tags, const float* __restrict__ trans,
                      float* __restrict__ out) {
    int b = blockIdx.x;
    int j = threadIdx.x;
    float Tcol[NTAG];
#pragma unroll
    for (int i = 0; i < NTAG; i++) Tcol[i] = (j < NTAG) ? trans[i * NTAG + j] : 0.f;
    float dcur = (j < NTAG) ? g_emit[0][b][j] : -1e30f;

    float ts = 0.f;
    for (int s = j; s < SEQ; s += 32) {
        int tg = tags[b * SEQ + s];
        ts += g_emit[s][b][tg];
        if (s < SEQ - 1) ts += trans[tg * NTAG + tags[b * SEQ + s + 1]];
    }
#pragma unroll
    for (int off = 16; off; off >>= 1) ts += __shfl_xor_sync(0xffffffffu, ts, off);

    for (int s = 1; s < SEQ; s++) {
        float v[NTAG];
#pragma unroll
        for (int i = 0; i < NTAG; i++)
            v[i] = __shfl_sync(0xffffffffu, dcur, i) + Tcol[i];
        float mx = v[0];
#pragma unroll
        for (int i = 1; i < NTAG; i++) mx = fmaxf(mx, v[i]);
        float sum = 0.f;
#pragma unroll
        for (int i = 0; i < NTAG; i++) sum += expf(v[i] - mx);
        float e = (j < NTAG) ? g_emit[s][b][j] : 0.f;
        dcur = e + mx + logf(sum);
    }

    float dd = (j < NTAG) ? dcur : -1e30f;
    float mm = dd;
#pragma unroll
    for (int off = 16; off; off >>= 1) mm = fmaxf(mm, __shfl_xor_sync(0xffffffffu, mm, off));
    float se = (j < NTAG) ? expf(dd - mm) : 0.f;
#pragma unroll
    for (int off = 16; off; off >>= 1) se += __shfl_xor_sync(0xffffffffu, se, off);
    if (j == 0) out[b] = mm + logf(se) - ts;
}

// ---------------- launch ----------------
extern "C" void kernel_launch(void* const* d_in, const int* in_sizes, int n_in,
                              void* d_out, int out_size) {
    const int*   sentences = (const int*)d_in[0];
    const int*   tags      = (const int*)d_in[1];
    const float* emb       = (const float*)d_in[2];
    const float* W_ih_f    = (const float*)d_in[3];
    const float* W_hh_f    = (const float*)d_in[4];
    const float* b_f       = (const float*)d_in[5];
    const float* W_ih_b    = (const float*)d_in[6];
    const float* W_hh_b    = (const float*)d_in[7];
    const float* b_b       = (const float*)d_in[8];
    const float* W_lin     = (const float*)d_in[9];
    const float* b_lin     = (const float*)d_in[10];
    const float* trans     = (const float*)d_in[11];
    float* out = (float*)d_out;

    int smem_ip = (HID * NB + HID * IP_ROWS) * 4;   // 148800 B
    int smem_rc = R_SMEMF * 4;                      // 221056 B
    cudaFuncSetAttribute(k_inproj, cudaFuncAttributeMaxDynamicSharedMemorySize, smem_ip);
    cudaFuncSetAttribute(k_recur,  cudaFuncAttributeMaxDynamicSharedMemorySize, smem_rc);

    k_gather<<<SEQ, 256>>>(sentences, emb);
    dim3 gip(IP_MB, SEQ, 2);
    k_inproj<<<gip, IP_THREADS, smem_ip>>>(W_ih_f, b_f, W_ih_b, b_b);
    k_recur<<<2 * RBG * RUS, R_THREADS, smem_rc>>>(W_hh_f, W_hh_b);
    k_emit<<<SEQ, 256>>>(W_lin, b_lin);
    k_crf<<<NB, 32>>>(tags, trans, out);
}

// round 6
// speedup vs baseline: 1.5234x; 1.5234x over previous
#include <cuda_runtime.h>
#include <cstdint>
#include <math.h>

#define SEQ 256
#define NB 64
#define HID 300
#define G4 1200
#define NTAG 12

// recurrence: 2 dirs x 8 batch-groups x 8 unit-slices = 128 CTAs
#define RBG 8           // batch groups
#define RUS 8           // unit slices
#define RBS 8           // batch per group
#define RUPC 38         // units per slice (last slice has 34)
#define R_P 76          // row pairs (152 gate rows / 2)
#define R_KCH 75
#define R_THREADS 320   // 304 active = 4 ksplit x 76 rowpairs

// input-projection config: 20 CTAs of 60 gate rows cover the 1200 rows
#define IP_MB 20
#define IP_ROWS 60
#define IP_THREADS 320

typedef unsigned long long ull;

__device__ __forceinline__ ull pack2(float lo, float hi) {
    ull r; asm("mov.b64 %0, {%1, %2};" : "=l"(r) : "f"(lo), "f"(hi)); return r;
}
__device__ __forceinline__ void unpack2(ull v, float& lo, float& hi) {
    asm("mov.b64 {%0, %1}, %2;" : "=f"(lo), "=f"(hi) : "l"(v));
}
__device__ __forceinline__ ull fma2(ull a, ull b, ull c) {
    ull d; asm("fma.rn.f32x2 %0, %1, %2, %3;" : "=l"(d) : "l"(a), "l"(b), "l"(c)); return d;
}
__device__ __forceinline__ ull add2(ull a, ull b) {
    ull d; asm("add.rn.f32x2 %0, %1, %2;" : "=l"(d) : "l"(a), "l"(b)); return d;
}
__device__ __forceinline__ float ftanh(float x) {
    float y; asm("tanh.approx.f32 %0, %1;" : "=f"(y) : "f"(x)); return y;
}
__device__ __forceinline__ float fsigm(float x) {
    return 0.5f * ftanh(0.5f * x) + 0.5f;
}

// ---------------- scratch (device globals; no allocations) ----------------
__device__ float g_XT[SEQ * HID * NB];             // x transposed: [s][k][b]
__device__ float g_G[2][SEQ][G4 * NB];             // input proj + bias: [d][s][row][b]
__device__ float g_hall[2][SEQ][RBG * HID * RBS];  // h: [d][s][group][u*8+bo]
__device__ float g_emit[SEQ][NB][NTAG];            // emissions
__device__ int   g_cnt2[16][32];                   // per (dir,group) counters, 128B-padded

extern __shared__ float sm[];

// ---------------- reset barrier counters ----------------
__global__ void k_reset() {
    if (threadIdx.x < 16) g_cnt2[threadIdx.x][0] = 0;
}

// ---------------- embedding gather + transpose ----------------
__global__ void k_gather(const int* __restrict__ sent, const float* __restrict__ emb) {
    int s = blockIdx.x;
    __shared__ float sx[64][33];
    __shared__ int rows[64];
    int t = threadIdx.x;  // 256
    if (t < 64) rows[t] = sent[t * SEQ + s];
    __syncthreads();
    for (int kc = 0; kc < 10; kc++) {
        int kbase = kc * 32;
        int width = HID - kbase; if (width > 32) width = 32;
        int kk = t & 31, bg = t >> 5;
        if (kk < width) {
            for (int b = bg; b < 64; b += 8)
                sx[b][kk] = emb[rows[b] * HID + kbase + kk];
        }
        __syncthreads();
        int b = t & 63, kg = t >> 6;
        for (int k2 = kg; k2 < width; k2 += 4)
            g_XT[(s * HID + kbase + k2) * NB + b] = sx[b][k2];
        __syncthreads();
    }
}

// ---------------- input projection GEMM: G[d][s][row][b] = W_ih @ x + bias ----------------
__global__ void __launch_bounds__(IP_THREADS, 1) k_inproj(
    const float* __restrict__ Wf, const float* __restrict__ bf,
    const float* __restrict__ Wb, const float* __restrict__ bb)
{
    int m = blockIdx.x, s = blockIdx.y, d = blockIdx.z;
    const float* W    = d ? Wb : Wf;
    const float* bias = d ? bb : bf;
    float* xs  = sm;               // 19200 floats
    float* ws  = sm + HID * NB;    // 18000 floats: ws[k*60 + r]
    int t = threadIdx.x;
    int u0 = m * 15;

    for (int idx = t; idx < HID * IP_ROWS; idx += IP_THREADS) {
        int k = idx / IP_ROWS, r = idx - k * IP_ROWS;
        int ul = r >> 2, gate = r & 3;
        ws[idx] = W[(gate * HID + u0 + ul) * HID + k];
    }
    {
        const float4* src = (const float4*)(g_XT + s * HID * NB);
        float4* dst = (float4*)xs;
        for (int idx = t; idx < HID * NB / 4; idx += IP_THREADS) dst[idx] = src[idx];
    }
    __syncthreads();

    int b = t & 63, rg = t >> 6;   // rg 0..4, owns rows rg*12 .. rg*12+11
    ull acc[6];
#pragma unroll
    for (int p = 0; p < 6; p++) acc[p] = 0ull;

    const ulonglong2* wp = ((const ulonglong2*)ws) + rg * 3;
    const float* xp = xs + b;
#pragma unroll 4
    for (int k = 0; k < HID; k++) {
        float hv = xp[k * NB];
        ull h2 = pack2(hv, hv);
        ulonglong2 w0 = wp[0], w1 = wp[1], w2 = wp[2];
        acc[0] = fma2(w0.x, h2, acc[0]);
        acc[1] = fma2(w0.y, h2, acc[1]);
        acc[2] = fma2(w1.x, h2, acc[2]);
        acc[3] = fma2(w1.y, h2, acc[3]);
        acc[4] = fma2(w2.x, h2, acc[4]);
        acc[5] = fma2(w2.y, h2, acc[5]);
        wp += 15;
    }

    float* Gd = g_G[d][s];
#pragma unroll
    for (int p = 0; p < 6; p++) {
        float v0, v1; unpack2(acc[p], v0, v1);
        int r0 = rg * 12 + 2 * p, r1 = r0 + 1;
        int row0 = (r0 & 3) * HID + u0 + (r0 >> 2);
        int row1 = (r1 & 3) * HID + u0 + (r1 >> 2);
        Gd[row0 * NB + b] = v0 + bias[row0];
        Gd[row1 * NB + b] = v1 + bias[row1];
    }
}

// ---------------- persistent LSTM recurrence, 2D (batch-group x unit-slice) ----------------
// CTA = (d, g, m). Owns units [m*38, m*38+cu) and batches [g*8, g*8+8).
// Group barrier: padded per-group counter, red.release arrive + ld.acquire poll.
__global__ void __launch_bounds__(R_THREADS, 1) k_recur(
    const float* __restrict__ Whf, const float* __restrict__ Whb)
{
    int bid = blockIdx.x;
    int d = bid >> 6;
    int g = (bid >> 3) & 7;
    int m = bid & 7;
    const float* W = d ? Whb : Whf;

    float* ws = sm;                    // ws[k*152 + r], r = ul*4+gate (row pairs packed)
    float* hs = sm + HID * 152;        // hs[k*8 + bo]
    ull*  red = (ull*)(hs + HID * RBS);

    int t = threadIdx.x;
    int u0 = m * RUPC;
    int cu = HID - u0; if (cu > RUPC) cu = RUPC;

    // stage weights (zero-padded beyond cu)
    for (int idx = t; idx < HID * 152; idx += R_THREADS) {
        int k = idx / 152, r = idx - k * 152;
        int ul = r >> 2, gate = r & 3;
        ws[idx] = (ul < cu) ? W[(gate * HID + u0 + ul) * HID + k] : 0.f;
    }
    __syncthreads();

    int ks = t / R_P;          // 0..3 active, 4 = spare
    int p  = t - ks * R_P;     // rowpair 0..75
    int k0 = (ks & 3) * R_KCH;
    int bp = (ks > 3) ? 3 : ks;        // batch-pair
    int ul = p >> 1;
    bool doer = (t < 304) && ((p & 1) == 0) && (ul < cu);
    int boff = g * RBS + bp * 2;
    float c0 = 0.f, c1 = 0.f;
    int* cnt = &g_cnt2[d * 8 + g][0];
    const ull* wsu = (const ull*)ws;
    const ulonglong2* hsu = (const ulonglong2*)hs;

    for (int step = 0; step < SEQ; step++) {
        int pos = d ? (SEQ - 1 - step) : step;
        const float* Gp = g_G[d][pos];

        // prefetch this step's G (hidden under the barrier wait)
        float2 Gv0, Gv1, Gv2, Gv3;
        if (doer) {
            int gb = (u0 + ul) * NB + boff;
            Gv0 = *(const float2*)(Gp + 0 * HID * NB + gb);
            Gv1 = *(const float2*)(Gp + 1 * HID * NB + gb);
            Gv2 = *(const float2*)(Gp + 2 * HID * NB + gb);
            Gv3 = *(const float2*)(Gp + 3 * HID * NB + gb);
        }

        float s0lo = 0.f, s0hi = 0.f, s1lo = 0.f, s1hi = 0.f;

        if (step > 0) {
            // wait for group h of previous step (contention-free padded counter)
            if (t == 0) {
                int target = RUS * step;
                int v;
                do {
                    asm volatile("ld.acquire.gpu.global.b32 %0, [%1];" : "=r"(v) : "l"(cnt) : "memory");
                    if (v < target) __nanosleep(20);
                } while (v < target);
            }
            __syncthreads();

            // stage group h slab (9.6KB)
            {
                int prev = d ? (SEQ - step) : (step - 1);
                const float4* src = (const float4*)(g_hall[d][prev] + g * (HID * RBS));
                float4* dst = (float4*)hs;
                for (int idx = t; idx < HID * RBS / 4; idx += R_THREADS) dst[idx] = src[idx];
            }
            __syncthreads();

            // partial GEMV: 2 rows x 8 batches per thread over 75 k's
            ull a00 = 0, a01 = 0, a02 = 0, a03 = 0;
            ull a10 = 0, a11 = 0, a12 = 0, a13 = 0;
#pragma unroll 5
            for (int kk = 0; kk < R_KCH; kk++) {
                int k = k0 + kk;
                ull w = wsu[k * R_P + p];
                float w0, w1; unpack2(w, w0, w1);
                ull w00 = pack2(w0, w0), w11 = pack2(w1, w1);
                ulonglong2 hA = hsu[k * 2];
                ulonglong2 hB = hsu[k * 2 + 1];
                a00 = fma2(w00, hA.x, a00); a01 = fma2(w00, hA.y, a01);
                a02 = fma2(w00, hB.x, a02); a03 = fma2(w00, hB.y, a03);
                a10 = fma2(w11, hA.x, a10); a11 = fma2(w11, hA.y, a11);
                a12 = fma2(w11, hB.x, a12); a13 = fma2(w11, hB.y, a13);
            }
            if (t < 304) {
                int base = p * 32 + ks;
                red[base + 0 * 8 + 0] = a00; red[base + 1 * 8 + 0] = a01;
                red[base + 2 * 8 + 0] = a02; red[base + 3 * 8 + 0] = a03;
                red[base + 0 * 8 + 4] = a10; red[base + 1 * 8 + 4] = a11;
                red[base + 2 * 8 + 4] = a12; red[base + 3 * 8 + 4] = a13;
            }
            __syncthreads();

            // phase2: thread (p, bp) sums 4 k-splits for rows 2p,2p+1 (2 batches)
            {
                const ulonglong2* r2 = (const ulonglong2*)red;
                int ib = (p * 8 + bp * 2) * 2;
                ulonglong2 q0 = r2[ib + 0], q1 = r2[ib + 1];
                ulonglong2 q2 = r2[ib + 2], q3 = r2[ib + 3];
                ull s0 = add2(add2(q0.x, q0.y), add2(q1.x, q1.y));
                ull s1 = add2(add2(q2.x, q2.y), add2(q3.x, q3.y));
                unpack2(s0, s0lo, s0hi);
                unpack2(s1, s1lo, s1hi);
            }
        }

        // exchange: even-p thread (gates i,f) pulls gates g,o from odd partner (t+1)
        float g2lo = __shfl_down_sync(0xffffffffu, s0lo, 1);
        float g2hi = __shfl_down_sync(0xffffffffu, s0hi, 1);
        float g3lo = __shfl_down_sync(0xffffffffu, s1lo, 1);
        float g3hi = __shfl_down_sync(0xffffffffu, s1hi, 1);

        if (doer) {
            float i0 = fsigm(s0lo + Gv0.x), i1 = fsigm(s0hi + Gv0.y);
            float f0 = fsigm(s1lo + Gv1.x), f1 = fsigm(s1hi + Gv1.y);
            float q0 = ftanh(g2lo + Gv2.x), q1 = ftanh(g2hi + Gv2.y);
            float o0 = fsigm(g3lo + Gv3.x), o1 = fsigm(g3hi + Gv3.y);
            c0 = f0 * c0 + i0 * q0;
            c1 = f1 * c1 + i1 * q1;
            float2 hv;
            hv.x = o0 * ftanh(c0);
            hv.y = o1 * ftanh(c1);
            *(float2*)(g_hall[d][pos] + g * (HID * RBS) + (u0 + ul) * RBS + bp * 2) = hv;
        }

        // arrive: release-semantics reduction (no explicit membar needed;
        // __syncthreads orders all CTA h-stores before t0's release)
        __syncthreads();
        if (t == 0)
            asm volatile("red.release.gpu.global.add.s32 [%0], 1;" :: "l"(cnt) : "memory");
    }
}

// ---------------- emissions: emit[s][b][j] = W_lin @ [h_f; h_b] + b_lin ----------------
__global__ void k_emit(const float* __restrict__ Wl, const float* __restrict__ bl) {
    int s = blockIdx.x, t = threadIdx.x;  // 256
    __shared__ float wl[600 * NTAG];
    __shared__ float red2[4 * NTAG * NB];
    for (int idx = t; idx < 600 * NTAG; idx += 256) {
        int k = idx / NTAG, j = idx - k * NTAG;
        wl[idx] = Wl[j * 600 + k];
    }
    __syncthreads();
    int b = t & 63, ksx = t >> 6;
    int gof = (b >> 3) * (HID * RBS) + (b & 7);
    float acc[NTAG];
#pragma unroll
    for (int j = 0; j < NTAG; j++) acc[j] = 0.f;
    const float* hf = g_hall[0][s];
    const float* hb = g_hall[1][s];
    int k0 = ksx * 150;
    for (int k = k0; k < k0 + 150; k++) {
        float v = (k < HID) ? hf[gof + k * RBS] : hb[gof + (k - HID) * RBS];
        const float4* w4 = (const float4*)(wl + k * NTAG);
#pragma unroll
        for (int q = 0; q < 3; q++) {
            float4 w = w4[q];
            acc[4 * q + 0] += w.x * v; acc[4 * q + 1] += w.y * v;
            acc[4 * q + 2] += w.z * v; acc[4 * q + 3] += w.w * v;
        }
    }
#pragma unroll
    for (int j = 0; j < NTAG; j++) red2[(ksx * NTAG + j) * NB + b] = acc[j];
    __syncthreads();
    for (int idx = t; idx < NTAG * NB; idx += 256) {
        int j = idx >> 6, b2 = idx & 63;
        float v = red2[(0 * NTAG + j) * NB + b2] + red2[(1 * NTAG + j) * NB + b2]
                + red2[(2 * NTAG + j) * NB + b2] + red2[(3 * NTAG + j) * NB + b2];
        g_emit[s][b2][j] = v + bl[j];
    }
}

// ---------------- CRF forward + gold score + loss (one warp per batch) ----------------
__global__ void k_crf(const int* __restrict__ tags, const float* __restrict__ trans,
                      float* __restrict__ out) {
    int b = blockIdx.x;
    int j = threadIdx.x;
    float Tcol[NTAG];
#pragma unroll
    for (int i = 0; i < NTAG; i++) Tcol[i] = (j < NTAG) ? trans[i * NTAG + j] : 0.f;
    float dcur = (j < NTAG) ? g_emit[0][b][j] : -1e30f;

    float ts = 0.f;
    for (int s = j; s < SEQ; s += 32) {
        int tg = tags[b * SEQ + s];
        ts += g_emit[s][b][tg];
        if (s < SEQ - 1) ts += trans[tg * NTAG + tags[b * SEQ + s + 1]];
    }
#pragma unroll
    for (int off = 16; off; off >>= 1) ts += __shfl_xor_sync(0xffffffffu, ts, off);

    for (int s = 1; s < SEQ; s++) {
        float v[NTAG];
#pragma unroll
        for (int i = 0; i < NTAG; i++)
            v[i] = __shfl_sync(0xffffffffu, dcur, i) + Tcol[i];
        float mx = v[0];
#pragma unroll
        for (int i = 1; i < NTAG; i++) mx = fmaxf(mx, v[i]);
        float sum = 0.f;
#pragma unroll
        for (int i = 0; i < NTAG; i++) sum += expf(v[i] - mx);
        float e = (j < NTAG) ? g_emit[s][b][j] : 0.f;
        dcur = e + mx + logf(sum);
    }

    float dd = (j < NTAG) ? dcur : -1e30f;
    float mm = dd;
#pragma unroll
    for (int off = 16; off; off >>= 1) mm = fmaxf(mm, __shfl_xor_sync(0xffffffffu, mm, off));
    float se = (j < NTAG) ? expf(dd - mm) : 0.f;
#pragma unroll
    for (int off = 16; off; off >>= 1) se += __shfl_xor_sync(0xffffffffu, se, off);
    if (j == 0) out[b] = mm + logf(se) - ts;
}

// ---------------- launch ----------------
extern "C" void kernel_launch(void* const* d_in, const int* in_sizes, int n_in,
                              void* d_out, int out_size) {
    const int*   sentences = (const int*)d_in[0];
    const int*   tags      = (const int*)d_in[1];
    const float* emb       = (const float*)d_in[2];
    const float* W_ih_f    = (const float*)d_in[3];
    const float* W_hh_f    = (const float*)d_in[4];
    const float* b_f       = (const float*)d_in[5];
    const float* W_ih_b    = (const float*)d_in[6];
    const float* W_hh_b    = (const float*)d_in[7];
    const float* b_b       = (const float*)d_in[8];
    const float* W_lin     = (const float*)d_in[9];
    const float* b_lin     = (const float*)d_in[10];
    const float* trans     = (const float*)d_in[11];
    float* out = (float*)d_out;

    int smem_ip = (HID * NB + HID * IP_ROWS) * 4;                      // 148800 B
    int smem_rc = (HID * 152 + HID * RBS + 2 * 2432) * 4;              // 211456 B
    cudaFuncSetAttribute(k_inproj, cudaFuncAttributeMaxDynamicSharedMemorySize, smem_ip);
    cudaFuncSetAttribute(k_recur,  cudaFuncAttributeMaxDynamicSharedMemorySize, smem_rc);

    k_reset<<<1, 32>>>();
    k_gather<<<SEQ, 256>>>(sentences, emb);
    dim3 gip(IP_MB, SEQ, 2);
    k_inproj<<<gip, IP_THREADS, smem_ip>>>(W_ih_f, b_f, W_ih_b, b_b);
    k_recur<<<2 * RBG * RUS, R_THREADS, smem_rc>>>(W_hh_f, W_hh_b);
    k_emit<<<SEQ, 256>>>(W_lin, b_lin);
    k_crf<<<NB, 32>>>(tags, trans, out);
}

// round 7
// speedup vs baseline: 1.6571x; 1.0877x over previous
#include <cuda_runtime.h>
#include <cstdint>
#include <math.h>

#define SEQ 256
#define NB 64
#define HID 300
#define G4 1200
#define NTAG 12

// recurrence: 2 dirs x 8 batch-groups x 8 unit-slices = 128 CTAs
#define RBG 8           // batch groups
#define RUS 8           // unit slices
#define RBS 8           // batch per group
#define RUPC 38         // units per slice (last slice has 34)
#define R_P 76          // row pairs (152 gate rows / 2)
#define R_KCH 75
#define R_THREADS 320   // 304 active = 4 ksplit x 76 rowpairs

// input projection: persistent weights, 20 m x 8 s-chunks x 2 dirs = 320 CTAs
#define IP_MB 20
#define IP_ROWS 60
#define IP_THREADS 320
#define IP_SC 32        // s per CTA
#define IP_KC 60        // k per chunk
#define IP_NKC 5        // chunks per s
#define IP_NIT (IP_SC * IP_NKC)   // 160 chunk iterations
#define IP_CHF (IP_KC * NB)       // 3840 floats per chunk

typedef unsigned long long ull;

__device__ __forceinline__ ull pack2(float lo, float hi) {
    ull r; asm("mov.b64 %0, {%1, %2};" : "=l"(r) : "f"(lo), "f"(hi)); return r;
}
__device__ __forceinline__ void unpack2(ull v, float& lo, float& hi) {
    asm("mov.b64 {%0, %1}, %2;" : "=f"(lo), "=f"(hi) : "l"(v));
}
__device__ __forceinline__ ull fma2(ull a, ull b, ull c) {
    ull d; asm("fma.rn.f32x2 %0, %1, %2, %3;" : "=l"(d) : "l"(a), "l"(b), "l"(c)); return d;
}
__device__ __forceinline__ ull add2(ull a, ull b) {
    ull d; asm("add.rn.f32x2 %0, %1, %2;" : "=l"(d) : "l"(a), "l"(b)); return d;
}
__device__ __forceinline__ float ftanh(float x) {
    float y; asm("tanh.approx.f32 %0, %1;" : "=f"(y) : "f"(x)); return y;
}
__device__ __forceinline__ float fsigm(float x) {
    return 0.5f * ftanh(0.5f * x) + 0.5f;
}
__device__ __forceinline__ uint32_t smem_u32_of(const void* p) {
    uint32_t a;
    asm("{ .reg .u64 t0; cvta.to.shared.u64 t0, %1; cvt.u32.u64 %0, t0; }" : "=r"(a) : "l"(p));
    return a;
}
__device__ __forceinline__ void cpasync16(uint32_t saddr, const void* g) {
    asm volatile("cp.async.cg.shared.global [%0], [%1], 16;" :: "r"(saddr), "l"(g));
}

// ---------------- scratch (device globals; no allocations) ----------------
__device__ float g_XT[SEQ * HID * NB];             // x transposed: [s][k][b]
__device__ float g_G[2][SEQ][G4 * NB];             // input proj + bias: [d][s][row][b]
__device__ float g_hall[2][SEQ][RBG * HID * RBS];  // h: [d][s][group][u*8+bo]
__device__ float g_emit[SEQ][NB][NTAG];            // emissions
__device__ int   g_cnt2[16][32];                   // per (dir,group) counters, 128B-padded

extern __shared__ float sm[];

// ---------------- reset barrier counters ----------------
__global__ void k_reset() {
    if (threadIdx.x < 16) g_cnt2[threadIdx.x][0] = 0;
}

// ---------------- embedding gather + transpose ----------------
__global__ void k_gather(const int* __restrict__ sent, const float* __restrict__ emb) {
    int s = blockIdx.x;
    __shared__ float sx[64][33];
    __shared__ int rows[64];
    int t = threadIdx.x;  // 256
    if (t < 64) rows[t] = sent[t * SEQ + s];
    __syncthreads();
    for (int kc = 0; kc < 10; kc++) {
        int kbase = kc * 32;
        int width = HID - kbase; if (width > 32) width = 32;
        int kk = t & 31, bg = t >> 5;
        if (kk < width) {
            for (int b = bg; b < 64; b += 8)
                sx[b][kk] = emb[rows[b] * HID + kbase + kk];
        }
        __syncthreads();
        int b = t & 63, kg = t >> 6;
        for (int k2 = kg; k2 < width; k2 += 4)
            g_XT[(s * HID + kbase + k2) * NB + b] = sx[b][k2];
        __syncthreads();
    }
}

// ---------------- input projection: persistent weights + cp.async x streaming ----------------
// CTA = (m, sc, d): 60 gate rows (u0..u0+14, 4 gates), 32 s values, k streamed in 60-chunks.
__global__ void __launch_bounds__(IP_THREADS, 2) k_inproj(
    const float* __restrict__ Wf, const float* __restrict__ bf,
    const float* __restrict__ Wb, const float* __restrict__ bb)
{
    int m = blockIdx.x, sc = blockIdx.y, d = blockIdx.z;
    const float* W    = d ? Wb : Wf;
    const float* bias = d ? bb : bf;
    float* ws  = sm;                    // 18000 floats: ws[k*60 + r]
    float* xb0 = sm + HID * IP_ROWS;    // 3840 floats
    float* xb1 = xb0 + IP_CHF;          // 3840 floats
    int t = threadIdx.x;
    int u0 = m * 15;

    uint32_t xb0a = smem_u32_of(xb0);
    uint32_t xb1a = smem_u32_of(xb1);

    // stage weights once: ws[k*60 + r], r = ul*4 + gate, row = gate*300 + u0 + ul
    for (int idx = t; idx < HID * IP_ROWS; idx += IP_THREADS) {
        int k = idx / IP_ROWS, r = idx - k * IP_ROWS;
        int ul = r >> 2, gate = r & 3;
        ws[idx] = W[(gate * HID + u0 + ul) * HID + k];
    }

    int b = t & 63, rg = t >> 6;   // rg 0..4, owns rows rg*12 .. rg*12+11

    // cache bias + output rows for this thread
    float bv[12];
    int rowv[12];
#pragma unroll
    for (int q = 0; q < 12; q++) {
        int r = rg * 12 + q;
        int row = (r & 3) * HID + u0 + (r >> 2);
        rowv[q] = row;
        bv[q] = bias[row];
    }

    int s0 = sc * IP_SC;
    const float* gx = g_XT + (long long)s0 * (HID * NB);

    // prefetch chunk 0
    {
        uint32_t dst = xb0a + t * 16;
        const float4* src = ((const float4*)gx) + t;
#pragma unroll
        for (int j = 0; j < 3; j++) {
            cpasync16(dst, src);
            dst += IP_THREADS * 16; src += IP_THREADS;
        }
        asm volatile("cp.async.commit_group;");
    }
    __syncthreads();   // ws ready

    ull acc[6];
#pragma unroll
    for (int p = 0; p < 6; p++) acc[p] = 0ull;

    const ulonglong2* wp = ((const ulonglong2*)ws) + rg * 3;
    int kc = 0, scur = s0;

    for (int it = 0; it < IP_NIT; it++) {
        // prefetch next chunk into the other buffer
        if (it < IP_NIT - 1) {
            uint32_t dst = (((it + 1) & 1) ? xb1a : xb0a) + t * 16;
            const float4* src = ((const float4*)(gx + (long long)(it + 1) * IP_CHF)) + t;
#pragma unroll
            for (int j = 0; j < 3; j++) {
                cpasync16(dst, src);
                dst += IP_THREADS * 16; src += IP_THREADS;
            }
            asm volatile("cp.async.commit_group;");
            asm volatile("cp.async.wait_group 1;");
        } else {
            asm volatile("cp.async.wait_group 0;");
        }
        __syncthreads();   // current chunk visible to all

        const float* xp = ((it & 1) ? xb1 : xb0) + b;
#pragma unroll 4
        for (int k = 0; k < IP_KC; k++) {
            float hv = xp[k * NB];
            ull h2 = pack2(hv, hv);
            ulonglong2 w0 = wp[0], w1 = wp[1], w2 = wp[2];
            acc[0] = fma2(w0.x, h2, acc[0]);
            acc[1] = fma2(w0.y, h2, acc[1]);
            acc[2] = fma2(w1.x, h2, acc[2]);
            acc[3] = fma2(w1.y, h2, acc[3]);
            acc[4] = fma2(w2.x, h2, acc[4]);
            acc[5] = fma2(w2.y, h2, acc[5]);
            wp += 15;  // 60 floats per k
        }

        if (++kc == IP_NKC) {
            // full K accumulated: store G for scur
            float* Gd = g_G[d][scur];
#pragma unroll
            for (int p = 0; p < 6; p++) {
                float v0, v1; unpack2(acc[p], v0, v1);
                Gd[rowv[2 * p] * NB + b]     = v0 + bv[2 * p];
                Gd[rowv[2 * p + 1] * NB + b] = v1 + bv[2 * p + 1];
                acc[p] = 0ull;
            }
            kc = 0; scur++;
            wp = ((const ulonglong2*)ws) + rg * 3;
        }
        __syncthreads();   // all reads of current buffer done before it is re-filled
    }
}

// ---------------- persistent LSTM recurrence, 2D (batch-group x unit-slice) ----------------
__global__ void __launch_bounds__(R_THREADS, 1) k_recur(
    const float* __restrict__ Whf, const float* __restrict__ Whb)
{
    int bid = blockIdx.x;
    int d = bid >> 6;
    int g = (bid >> 3) & 7;
    int m = bid & 7;
    const float* W = d ? Whb : Whf;

    float* ws = sm;                    // ws[k*152 + r], r = ul*4+gate (row pairs packed)
    float* hs = sm + HID * 152;        // hs[k*8 + bo]
    ull*  red = (ull*)(hs + HID * RBS);

    int t = threadIdx.x;
    int u0 = m * RUPC;
    int cu = HID - u0; if (cu > RUPC) cu = RUPC;

    for (int idx = t; idx < HID * 152; idx += R_THREADS) {
        int k = idx / 152, r = idx - k * 152;
        int ul = r >> 2, gate = r & 3;
        ws[idx] = (ul < cu) ? W[(gate * HID + u0 + ul) * HID + k] : 0.f;
    }
    __syncthreads();

    int ks = t / R_P;          // 0..3 active, 4 = spare
    int p  = t - ks * R_P;     // rowpair 0..75
    int k0 = (ks & 3) * R_KCH;
    int bp = (ks > 3) ? 3 : ks;        // batch-pair
    int ul = p >> 1;
    bool doer = (t < 304) && ((p & 1) == 0) && (ul < cu);
    int boff = g * RBS + bp * 2;
    float c0 = 0.f, c1 = 0.f;
    int* cnt = &g_cnt2[d * 8 + g][0];
    const ull* wsu = (const ull*)ws;
    const ulonglong2* hsu = (const ulonglong2*)hs;

    for (int step = 0; step < SEQ; step++) {
        int pos = d ? (SEQ - 1 - step) : step;
        const float* Gp = g_G[d][pos];

        float2 Gv0, Gv1, Gv2, Gv3;
        if (doer) {
            int gb = (u0 + ul) * NB + boff;
            Gv0 = *(const float2*)(Gp + 0 * HID * NB + gb);
            Gv1 = *(const float2*)(Gp + 1 * HID * NB + gb);
            Gv2 = *(const float2*)(Gp + 2 * HID * NB + gb);
            Gv3 = *(const float2*)(Gp + 3 * HID * NB + gb);
        }

        float s0lo = 0.f, s0hi = 0.f, s1lo = 0.f, s1hi = 0.f;

        if (step > 0) {
            if (t == 0) {
                int target = RUS * step;
                int v;
                do {
                    asm volatile("ld.acquire.gpu.global.b32 %0, [%1];" : "=r"(v) : "l"(cnt) : "memory");
                    if (v < target) __nanosleep(20);
                } while (v < target);
            }
            __syncthreads();

            {
                int prev = d ? (SEQ - step) : (step - 1);
                const float4* src = (const float4*)(g_hall[d][prev] + g * (HID * RBS));
                float4* dst = (float4*)hs;
                for (int idx = t; idx < HID * RBS / 4; idx += R_THREADS) dst[idx] = src[idx];
            }
            __syncthreads();

            ull a00 = 0, a01 = 0, a02 = 0, a03 = 0;
            ull a10 = 0, a11 = 0, a12 = 0, a13 = 0;
#pragma unroll 5
            for (int kk = 0; kk < R_KCH; kk++) {
                int k = k0 + kk;
                ull w = wsu[k * R_P + p];
                float w0, w1; unpack2(w, w0, w1);
                ull w00 = pack2(w0, w0), w11 = pack2(w1, w1);
                ulonglong2 hA = hsu[k * 2];
                ulonglong2 hB = hsu[k * 2 + 1];
                a00 = fma2(w00, hA.x, a00); a01 = fma2(w00, hA.y, a01);
                a02 = fma2(w00, hB.x, a02); a03 = fma2(w00, hB.y, a03);
                a10 = fma2(w11, hA.x, a10); a11 = fma2(w11, hA.y, a11);
                a12 = fma2(w11, hB.x, a12); a13 = fma2(w11, hB.y, a13);
            }
            if (t < 304) {
                int base = p * 32 + ks;
                red[base + 0 * 8 + 0] = a00; red[base + 1 * 8 + 0] = a01;
                red[base + 2 * 8 + 0] = a02; red[base + 3 * 8 + 0] = a03;
                red[base + 0 * 8 + 4] = a10; red[base + 1 * 8 + 4] = a11;
                red[base + 2 * 8 + 4] = a12; red[base + 3 * 8 + 4] = a13;
            }
            __syncthreads();

            {
                const ulonglong2* r2 = (const ulonglong2*)red;
                int ib = (p * 8 + bp * 2) * 2;
                ulonglong2 q0 = r2[ib + 0], q1 = r2[ib + 1];
                ulonglong2 q2 = r2[ib + 2], q3 = r2[ib + 3];
                ull s0 = add2(add2(q0.x, q0.y), add2(q1.x, q1.y));
                ull s1 = add2(add2(q2.x, q2.y), add2(q3.x, q3.y));
                unpack2(s0, s0lo, s0hi);
                unpack2(s1, s1lo, s1hi);
            }
        }

        float g2lo = __shfl_down_sync(0xffffffffu, s0lo, 1);
        float g2hi = __shfl_down_sync(0xffffffffu, s0hi, 1);
        float g3lo = __shfl_down_sync(0xffffffffu, s1lo, 1);
        float g3hi = __shfl_down_sync(0xffffffffu, s1hi, 1);

        if (doer) {
            float i0 = fsigm(s0lo + Gv0.x), i1 = fsigm(s0hi + Gv0.y);
            float f0 = fsigm(s1lo + Gv1.x), f1 = fsigm(s1hi + Gv1.y);
            float q0 = ftanh(g2lo + Gv2.x), q1 = ftanh(g2hi + Gv2.y);
            float o0 = fsigm(g3lo + Gv3.x), o1 = fsigm(g3hi + Gv3.y);
            c0 = f0 * c0 + i0 * q0;
            c1 = f1 * c1 + i1 * q1;
            float2 hv;
            hv.x = o0 * ftanh(c0);
            hv.y = o1 * ftanh(c1);
            *(float2*)(g_hall[d][pos] + g * (HID * RBS) + (u0 + ul) * RBS + bp * 2) = hv;
        }

        __syncthreads();
        if (t == 0)
            asm volatile("red.release.gpu.global.add.s32 [%0], 1;" :: "l"(cnt) : "memory");
    }
}

// ---------------- emissions: emit[s][b][j] = W_lin @ [h_f; h_b] + b_lin ----------------
__global__ void k_emit(const float* __restrict__ Wl, const float* __restrict__ bl) {
    int s = blockIdx.x, t = threadIdx.x;  // 256
    __shared__ float wl[600 * NTAG];
    __shared__ float red2[4 * NTAG * NB];
    for (int idx = t; idx < 600 * NTAG; idx += 256) {
        int k = idx / NTAG, j = idx - k * NTAG;
        wl[idx] = Wl[j * 600 + k];
    }
    __syncthreads();
    int b = t & 63, ksx = t >> 6;
    int gof = (b >> 3) * (HID * RBS) + (b & 7);
    float acc[NTAG];
#pragma unroll
    for (int j = 0; j < NTAG; j++) acc[j] = 0.f;
    const float* hf = g_hall[0][s];
    const float* hb = g_hall[1][s];
    int k0 = ksx * 150;
    for (int k = k0; k < k0 + 150; k++) {
        float v = (k < HID) ? hf[gof + k * RBS] : hb[gof + (k - HID) * RBS];
        const float4* w4 = (const float4*)(wl + k * NTAG);
#pragma unroll
        for (int q = 0; q < 3; q++) {
            float4 w = w4[q];
            acc[4 * q + 0] += w.x * v; acc[4 * q + 1] += w.y * v;
            acc[4 * q + 2] += w.z * v; acc[4 * q + 3] += w.w * v;
        }
    }
#pragma unroll
    for (int j = 0; j < NTAG; j++) red2[(ksx * NTAG + j) * NB + b] = acc[j];
    __syncthreads();
    for (int idx = t; idx < NTAG * NB; idx += 256) {
        int j = idx >> 6, b2 = idx & 63;
        float v = red2[(0 * NTAG + j) * NB + b2] + red2[(1 * NTAG + j) * NB + b2]
                + red2[(2 * NTAG + j) * NB + b2] + red2[(3 * NTAG + j) * NB + b2];
        g_emit[s][b2][j] = v + bl[j];
    }
}

// ---------------- CRF forward + gold score + loss (one warp per batch) ----------------
__global__ void k_crf(const int* __restrict__ tags, const float* __restrict__ trans,
                      float* __restrict__ out) {
    int b = blockIdx.x;
    int j = threadIdx.x;
    float Tcol[NTAG];
#pragma unroll
    for (int i = 0; i < NTAG; i++) Tcol[i] = (j < NTAG) ? trans[i * NTAG + j] : 0.f;
    float dcur = (j < NTAG) ? g_emit[0][b][j] : -1e30f;

    float ts = 0.f;
    for (int s = j; s < SEQ; s += 32) {
        int tg = tags[b * SEQ + s];
        ts += g_emit[s][b][tg];
        if (s < SEQ - 1) ts += trans[tg * NTAG + tags[b * SEQ + s + 1]];
    }
#pragma unroll
    for (int off = 16; off; off >>= 1) ts += __shfl_xor_sync(0xffffffffu, ts, off);

    for (int s = 1; s < SEQ; s++) {
        float v[NTAG];
#pragma unroll
        for (int i = 0; i < NTAG; i++)
            v[i] = __shfl_sync(0xffffffffu, dcur, i) + Tcol[i];
        float mx = v[0];
#pragma unroll
        for (int i = 1; i < NTAG; i++) mx = fmaxf(mx, v[i]);
        float sum = 0.f;
#pragma unroll
        for (int i = 0; i < NTAG; i++) sum += expf(v[i] - mx);
        float e = (j < NTAG) ? g_emit[s][b][j] : 0.f;
        dcur = e + mx + logf(sum);
    }

    float dd = (j < NTAG) ? dcur : -1e30f;
    float mm = dd;
#pragma unroll
    for (int off = 16; off; off >>= 1) mm = fmaxf(mm, __shfl_xor_sync(0xffffffffu, mm, off));
    float se = (j < NTAG) ? expf(dd - mm) : 0.f;
#pragma unroll
    for (int off = 16; off; off >>= 1) se += __shfl_xor_sync(0xffffffffu, se, off);
    if (j == 0) out[b] = mm + logf(se) - ts;
}

// ---------------- launch ----------------
extern "C" void kernel_launch(void* const* d_in, const int* in_sizes, int n_in,
                              void* d_out, int out_size) {
    const int*   sentences = (const int*)d_in[0];
    const int*   tags      = (const int*)d_in[1];
    const float* emb       = (const float*)d_in[2];
    const float* W_ih_f    = (const float*)d_in[3];
    const float* W_hh_f    = (const float*)d_in[4];
    const float* b_f       = (const float*)d_in[5];
    const float* W_ih_b    = (const float*)d_in[6];
    const float* W_hh_b    = (const float*)d_in[7];
    const float* b_b       = (const float*)d_in[8];
    const float* W_lin     = (const float*)d_in[9];
    const float* b_lin     = (const float*)d_in[10];
    const float* trans     = (const float*)d_in[11];
    float* out = (float*)d_out;

    int smem_ip = (HID * IP_ROWS + 2 * IP_CHF) * 4;                    // 102720 B
    int smem_rc = (HID * 152 + HID * RBS + 2 * 2432) * 4;              // 211456 B
    cudaFuncSetAttribute(k_inproj, cudaFuncAttributeMaxDynamicSharedMemorySize, smem_ip);
    cudaFuncSetAttribute(k_recur,  cudaFuncAttributeMaxDynamicSharedMemorySize, smem_rc);

    k_reset<<<1, 32>>>();
    k_gather<<<SEQ, 256>>>(sentences, emb);
    dim3 gip(IP_MB, SEQ / IP_SC, 2);
    k_inproj<<<gip, IP_THREADS, smem_ip>>>(W_ih_f, b_f, W_ih_b, b_b);
    k_recur<<<2 * RBG * RUS, R_THREADS, smem_rc>>>(W_hh_f, W_hh_b);
    k_emit<<<SEQ, 256>>>(W_lin, b_lin);
    k_crf<<<NB, 32>>>(tags, trans, out);
}

// round 8
// speedup vs baseline: 1.8145x; 1.0950x over previous
#include <cuda_runtime.h>
#include <cstdint>
#include <math.h>

#define SEQ 256
#define NB 64
#define HID 300
#define G4 1200
#define NTAG 12

// recurrence: 2 dirs x 8 batch-groups x 8 unit-slices = 128 CTAs
#define RBG 8           // batch groups
#define RUS 8           // unit slices
#define RBS 8           // batch per group
#define RUPC 38         // units per slice (last slice has 34)
#define R_P 76          // row pairs (152 gate rows / 2)
#define R_KCH 75
#define R_THREADS 320   // 304 active = 4 ksplit x 76 rowpairs

// input projection: persistent weights; 7 seq-splits x 20 m x 2 dirs = 280 CTAs (one wave)
#define IP_MB 20
#define IP_ROWS 60
#define IP_THREADS 320
#define IP_JS 7         // CTAs sharing one weight tile (sequence split)
#define IP_SC 37        // s per CTA (last CTA: 34)
#define IP_KC 60        // k per chunk
#define IP_NKC 5        // chunks per s
#define IP_CHF (IP_KC * NB)       // 3840 floats per chunk

typedef unsigned long long ull;

__device__ __forceinline__ ull pack2(float lo, float hi) {
    ull r; asm("mov.b64 %0, {%1, %2};" : "=l"(r) : "f"(lo), "f"(hi)); return r;
}
__device__ __forceinline__ void unpack2(ull v, float& lo, float& hi) {
    asm("mov.b64 {%0, %1}, %2;" : "=f"(lo), "=f"(hi) : "l"(v));
}
__device__ __forceinline__ ull fma2(ull a, ull b, ull c) {
    ull d; asm("fma.rn.f32x2 %0, %1, %2, %3;" : "=l"(d) : "l"(a), "l"(b), "l"(c)); return d;
}
__device__ __forceinline__ ull add2(ull a, ull b) {
    ull d; asm("add.rn.f32x2 %0, %1, %2;" : "=l"(d) : "l"(a), "l"(b)); return d;
}
__device__ __forceinline__ float ftanh(float x) {
    float y; asm("tanh.approx.f32 %0, %1;" : "=f"(y) : "f"(x)); return y;
}
__device__ __forceinline__ float fsigm(float x) {
    return 0.5f * ftanh(0.5f * x) + 0.5f;
}
__device__ __forceinline__ uint32_t smem_u32_of(const void* p) {
    uint32_t a;
    asm("{ .reg .u64 t0; cvta.to.shared.u64 t0, %1; cvt.u32.u64 %0, t0; }" : "=r"(a) : "l"(p));
    return a;
}
__device__ __forceinline__ void cpasync16(uint32_t saddr, const void* g) {
    asm volatile("cp.async.cg.shared.global [%0], [%1], 16;" :: "r"(saddr), "l"(g));
}

// ---------------- scratch (device globals; no allocations) ----------------
__device__ float g_XT[SEQ * HID * NB];             // x transposed: [s][k][b]
__device__ float g_G[2][SEQ][G4 * NB];             // input proj + bias: [d][s][row][b]
__device__ float g_hall[2][SEQ][RBG * HID * RBS];  // h: [d][s][group][u*8+bo]
__device__ float g_emit[SEQ][NB][NTAG];            // emissions
__device__ int   g_cnt2[16][32];                   // per (dir,group) counters, 128B-padded

extern __shared__ float sm[];

// ---------------- reset barrier counters ----------------
__global__ void k_reset() {
    if (threadIdx.x < 16) g_cnt2[threadIdx.x][0] = 0;
}

// ---------------- embedding gather + transpose ----------------
__global__ void k_gather(const int* __restrict__ sent, const float* __restrict__ emb) {
    int s = blockIdx.x;
    __shared__ float sx[64][33];
    __shared__ int rows[64];
    int t = threadIdx.x;  // 256
    if (t < 64) rows[t] = sent[t * SEQ + s];
    __syncthreads();
    for (int kc = 0; kc < 10; kc++) {
        int kbase = kc * 32;
        int width = HID - kbase; if (width > 32) width = 32;
        int kk = t & 31, bg = t >> 5;
        if (kk < width) {
            for (int b = bg; b < 64; b += 8)
                sx[b][kk] = emb[rows[b] * HID + kbase + kk];
        }
        __syncthreads();
        int b = t & 63, kg = t >> 6;
        for (int k2 = kg; k2 < width; k2 += 4)
            g_XT[(s * HID + kbase + k2) * NB + b] = sx[b][k2];
        __syncthreads();
    }
}

// ---------------- input projection: persistent weights + cp.async x streaming ----------------
// CTA = (j, m, d): 60 gate rows, s in [j*37, ...) (37 or 34 values), k streamed in 60-chunks.
// 280 CTAs, 2/SM -> single wave.
__global__ void __launch_bounds__(IP_THREADS, 2) k_inproj(
    const float* __restrict__ Wf, const float* __restrict__ bf,
    const float* __restrict__ Wb, const float* __restrict__ bb)
{
    int j = blockIdx.x, m = blockIdx.y, d = blockIdx.z;
    const float* W    = d ? Wb : Wf;
    const float* bias = d ? bb : bf;
    float* ws  = sm;                    // 18000 floats: ws[k*60 + r]
    float* xb0 = sm + HID * IP_ROWS;    // 3840 floats
    float* xb1 = xb0 + IP_CHF;          // 3840 floats
    int t = threadIdx.x;
    int u0 = m * 15;

    int s0 = j * IP_SC;
    int ns = SEQ - s0; if (ns > IP_SC) ns = IP_SC;
    int nit = ns * IP_NKC;

    uint32_t xb0a = smem_u32_of(xb0);
    uint32_t xb1a = smem_u32_of(xb1);

    // stage weights once: ws[k*60 + r], r = ul*4 + gate, row = gate*300 + u0 + ul
    for (int idx = t; idx < HID * IP_ROWS; idx += IP_THREADS) {
        int k = idx / IP_ROWS, r = idx - k * IP_ROWS;
        int ul = r >> 2, gate = r & 3;
        ws[idx] = W[(gate * HID + u0 + ul) * HID + k];
    }

    int b = t & 63, rg = t >> 6;   // rg 0..4, owns rows rg*12 .. rg*12+11

    // cache bias + output rows for this thread
    float bv[12];
    int rowv[12];
#pragma unroll
    for (int q = 0; q < 12; q++) {
        int r = rg * 12 + q;
        int row = (r & 3) * HID + u0 + (r >> 2);
        rowv[q] = row;
        bv[q] = bias[row];
    }

    const float* gx = g_XT + (long long)s0 * (HID * NB);

    // prefetch chunk 0
    {
        uint32_t dst = xb0a + t * 16;
        const float4* src = ((const float4*)gx) + t;
#pragma unroll
        for (int q = 0; q < 3; q++) {
            cpasync16(dst, src);
            dst += IP_THREADS * 16; src += IP_THREADS;
        }
        asm volatile("cp.async.commit_group;");
    }
    __syncthreads();   // ws ready

    ull acc[6];
#pragma unroll
    for (int p = 0; p < 6; p++) acc[p] = 0ull;

    const ulonglong2* wp = ((const ulonglong2*)ws) + rg * 3;
    int kc = 0, scur = s0;

    for (int it = 0; it < nit; it++) {
        // prefetch next chunk into the other buffer
        if (it < nit - 1) {
            uint32_t dst = (((it + 1) & 1) ? xb1a : xb0a) + t * 16;
            const float4* src = ((const float4*)(gx + (long long)(it + 1) * IP_CHF)) + t;
#pragma unroll
            for (int q = 0; q < 3; q++) {
                cpasync16(dst, src);
                dst += IP_THREADS * 16; src += IP_THREADS;
            }
            asm volatile("cp.async.commit_group;");
            asm volatile("cp.async.wait_group 1;");
        } else {
            asm volatile("cp.async.wait_group 0;");
        }
        __syncthreads();   // current chunk visible to all

        const float* xp = ((it & 1) ? xb1 : xb0) + b;
#pragma unroll 4
        for (int k = 0; k < IP_KC; k++) {
            float hv = xp[k * NB];
            ull h2 = pack2(hv, hv);
            ulonglong2 w0 = wp[0], w1 = wp[1], w2 = wp[2];
            acc[0] = fma2(w0.x, h2, acc[0]);
            acc[1] = fma2(w0.y, h2, acc[1]);
            acc[2] = fma2(w1.x, h2, acc[2]);
            acc[3] = fma2(w1.y, h2, acc[3]);
            acc[4] = fma2(w2.x, h2, acc[4]);
            acc[5] = fma2(w2.y, h2, acc[5]);
            wp += 15;  // 60 floats per k
        }

        if (++kc == IP_NKC) {
            // full K accumulated: store G for scur
            float* Gd = g_G[d][scur];
#pragma unroll
            for (int p = 0; p < 6; p++) {
                float v0, v1; unpack2(acc[p], v0, v1);
                Gd[rowv[2 * p] * NB + b]     = v0 + bv[2 * p];
                Gd[rowv[2 * p + 1] * NB + b] = v1 + bv[2 * p + 1];
                acc[p] = 0ull;
            }
            kc = 0; scur++;
            wp = ((const ulonglong2*)ws) + rg * 3;
        }
        __syncthreads();   // all reads of current buffer done before it is re-filled
    }
}

// ---------------- persistent LSTM recurrence, 2D (batch-group x unit-slice) ----------------
__global__ void __launch_bounds__(R_THREADS, 1) k_recur(
    const float* __restrict__ Whf, const float* __restrict__ Whb)
{
    int bid = blockIdx.x;
    int d = bid >> 6;
    int g = (bid >> 3) & 7;
    int m = bid & 7;
    const float* W = d ? Whb : Whf;

    float* ws = sm;                    // ws[k*152 + r], r = ul*4+gate (row pairs packed)
    float* hs = sm + HID * 152;        // hs[k*8 + bo]
    ull*  red = (ull*)(hs + HID * RBS);

    int t = threadIdx.x;
    int u0 = m * RUPC;
    int cu = HID - u0; if (cu > RUPC) cu = RUPC;

    for (int idx = t; idx < HID * 152; idx += R_THREADS) {
        int k = idx / 152, r = idx - k * 152;
        int ul = r >> 2, gate = r & 3;
        ws[idx] = (ul < cu) ? W[(gate * HID + u0 + ul) * HID + k] : 0.f;
    }
    __syncthreads();

    int ks = t / R_P;          // 0..3 active, 4 = spare
    int p  = t - ks * R_P;     // rowpair 0..75
    int k0 = (ks & 3) * R_KCH;
    int bp = (ks > 3) ? 3 : ks;        // batch-pair
    int ul = p >> 1;
    bool doer = (t < 304) && ((p & 1) == 0) && (ul < cu);
    int boff = g * RBS + bp * 2;
    float c0 = 0.f, c1 = 0.f;
    int* cnt = &g_cnt2[d * 8 + g][0];
    const ull* wsu = (const ull*)ws;
    const ulonglong2* hsu = (const ulonglong2*)hs;

    for (int step = 0; step < SEQ; step++) {
        int pos = d ? (SEQ - 1 - step) : step;
        const float* Gp = g_G[d][pos];

        float2 Gv0, Gv1, Gv2, Gv3;
        if (doer) {
            int gb = (u0 + ul) * NB + boff;
            Gv0 = *(const float2*)(Gp + 0 * HID * NB + gb);
            Gv1 = *(const float2*)(Gp + 1 * HID * NB + gb);
            Gv2 = *(const float2*)(Gp + 2 * HID * NB + gb);
            Gv3 = *(const float2*)(Gp + 3 * HID * NB + gb);
        }

        float s0lo = 0.f, s0hi = 0.f, s1lo = 0.f, s1hi = 0.f;

        if (step > 0) {
            if (t == 0) {
                int target = RUS * step;
                int v;
                do {
                    asm volatile("ld.acquire.gpu.global.b32 %0, [%1];" : "=r"(v) : "l"(cnt) : "memory");
                    if (v < target) __nanosleep(20);
                } while (v < target);
            }
            __syncthreads();

            {
                int prev = d ? (SEQ - step) : (step - 1);
                const float4* src = (const float4*)(g_hall[d][prev] + g * (HID * RBS));
                float4* dst = (float4*)hs;
                for (int idx = t; idx < HID * RBS / 4; idx += R_THREADS) dst[idx] = src[idx];
            }
            __syncthreads();

            ull a00 = 0, a01 = 0, a02 = 0, a03 = 0;
            ull a10 = 0, a11 = 0, a12 = 0, a13 = 0;
#pragma unroll 5
            for (int kk = 0; kk < R_KCH; kk++) {
                int k = k0 + kk;
                ull w = wsu[k * R_P + p];
                float w0, w1; unpack2(w, w0, w1);
                ull w00 = pack2(w0, w0), w11 = pack2(w1, w1);
                ulonglong2 hA = hsu[k * 2];
                ulonglong2 hB = hsu[k * 2 + 1];
                a00 = fma2(w00, hA.x, a00); a01 = fma2(w00, hA.y, a01);
                a02 = fma2(w00, hB.x, a02); a03 = fma2(w00, hB.y, a03);
                a10 = fma2(w11, hA.x, a10); a11 = fma2(w11, hA.y, a11);
                a12 = fma2(w11, hB.x, a12); a13 = fma2(w11, hB.y, a13);
            }
            if (t < 304) {
                int base = p * 32 + ks;
                red[base + 0 * 8 + 0] = a00; red[base + 1 * 8 + 0] = a01;
                red[base + 2 * 8 + 0] = a02; red[base + 3 * 8 + 0] = a03;
                red[base + 0 * 8 + 4] = a10; red[base + 1 * 8 + 4] = a11;
                red[base + 2 * 8 + 4] = a12; red[base + 3 * 8 + 4] = a13;
            }
            __syncthreads();

            {
                const ulonglong2* r2 = (const ulonglong2*)red;
                int ib = (p * 8 + bp * 2) * 2;
                ulonglong2 q0 = r2[ib + 0], q1 = r2[ib + 1];
                ulonglong2 q2 = r2[ib + 2], q3 = r2[ib + 3];
                ull s0 = add2(add2(q0.x, q0.y), add2(q1.x, q1.y));
                ull s1 = add2(add2(q2.x, q2.y), add2(q3.x, q3.y));
                unpack2(s0, s0lo, s0hi);
                unpack2(s1, s1lo, s1hi);
            }
        }

        float g2lo = __shfl_down_sync(0xffffffffu, s0lo, 1);
        float g2hi = __shfl_down_sync(0xffffffffu, s0hi, 1);
        float g3lo = __shfl_down_sync(0xffffffffu, s1lo, 1);
        float g3hi = __shfl_down_sync(0xffffffffu, s1hi, 1);

        if (doer) {
            float i0 = fsigm(s0lo + Gv0.x), i1 = fsigm(s0hi + Gv0.y);
            float f0 = fsigm(s1lo + Gv1.x), f1 = fsigm(s1hi + Gv1.y);
            float q0 = ftanh(g2lo + Gv2.x), q1 = ftanh(g2hi + Gv2.y);
            float o0 = fsigm(g3lo + Gv3.x), o1 = fsigm(g3hi + Gv3.y);
            c0 = f0 * c0 + i0 * q0;
            c1 = f1 * c1 + i1 * q1;
            float2 hv;
            hv.x = o0 * ftanh(c0);
            hv.y = o1 * ftanh(c1);
            *(float2*)(g_hall[d][pos] + g * (HID * RBS) + (u0 + ul) * RBS + bp * 2) = hv;
        }

        __syncthreads();
        if (t == 0)
            asm volatile("red.release.gpu.global.add.s32 [%0], 1;" :: "l"(cnt) : "memory");
    }
}

// ---------------- emissions: emit[s][b][j] = W_lin @ [h_f; h_b] + b_lin ----------------
__global__ void k_emit(const float* __restrict__ Wl, const float* __restrict__ bl) {
    int s = blockIdx.x, t = threadIdx.x;  // 256
    __shared__ float wl[600 * NTAG];
    __shared__ float red2[4 * NTAG * NB];
    for (int idx = t; idx < 600 * NTAG; idx += 256) {
        int k = idx / NTAG, j = idx - k * NTAG;
        wl[idx] = Wl[j * 600 + k];
    }
    __syncthreads();
    int b = t & 63, ksx = t >> 6;
    int gof = (b >> 3) * (HID * RBS) + (b & 7);
    float acc[NTAG];
#pragma unroll
    for (int j = 0; j < NTAG; j++) acc[j] = 0.f;
    const float* hf = g_hall[0][s];
    const float* hb = g_hall[1][s];
    int k0 = ksx * 150;
    for (int k = k0; k < k0 + 150; k++) {
        float v = (k < HID) ? hf[gof + k * RBS] : hb[gof + (k - HID) * RBS];
        const float4* w4 = (const float4*)(wl + k * NTAG);
#pragma unroll
        for (int q = 0; q < 3; q++) {
            float4 w = w4[q];
            acc[4 * q + 0] += w.x * v; acc[4 * q + 1] += w.y * v;
            acc[4 * q + 2] += w.z * v; acc[4 * q + 3] += w.w * v;
        }
    }
#pragma unroll
    for (int j = 0; j < NTAG; j++) red2[(ksx * NTAG + j) * NB + b] = acc[j];
    __syncthreads();
    for (int idx = t; idx < NTAG * NB; idx += 256) {
        int j = idx >> 6, b2 = idx & 63;
        float v = red2[(0 * NTAG + j) * NB + b2] + red2[(1 * NTAG + j) * NB + b2]
                + red2[(2 * NTAG + j) * NB + b2] + red2[(3 * NTAG + j) * NB + b2];
        g_emit[s][b2][j] = v + bl[j];
    }
}

// ---------------- CRF forward + gold score + loss (one warp per batch) ----------------
__global__ void k_crf(const int* __restrict__ tags, const float* __restrict__ trans,
                      float* __restrict__ out) {
    int b = blockIdx.x;
    int j = threadIdx.x;
    float Tcol[NTAG];
#pragma unroll
    for (int i = 0; i < NTAG; i++) Tcol[i] = (j < NTAG) ? trans[i * NTAG + j] : 0.f;
    float dcur = (j < NTAG) ? g_emit[0][b][j] : -1e30f;

    float ts = 0.f;
    for (int s = j; s < SEQ; s += 32) {
        int tg = tags[b * SEQ + s];
        ts += g_emit[s][b][tg];
        if (s < SEQ - 1) ts += trans[tg * NTAG + tags[b * SEQ + s + 1]];
    }
#pragma unroll
    for (int off = 16; off; off >>= 1) ts += __shfl_xor_sync(0xffffffffu, ts, off);

    for (int s = 1; s < SEQ; s++) {
        float v[NTAG];
#pragma unroll
        for (int i = 0; i < NTAG; i++)
            v[i] = __shfl_sync(0xffffffffu, dcur, i) + Tcol[i];
        float mx = v[0];
#pragma unroll
        for (int i = 1; i < NTAG; i++) mx = fmaxf(mx, v[i]);
        float sum = 0.f;
#pragma unroll
        for (int i = 0; i < NTAG; i++) sum += expf(v[i] - mx);
        float e = (j < NTAG) ? g_emit[s][b][j] : 0.f;
        dcur = e + mx + logf(sum);
    }

    float dd = (j < NTAG) ? dcur : -1e30f;
    float mm = dd;
#pragma unroll
    for (int off = 16; off; off >>= 1) mm = fmaxf(mm, __shfl_xor_sync(0xffffffffu, mm, off));
    float se = (j < NTAG) ? expf(dd - mm) : 0.f;
#pragma unroll
    for (int off = 16; off; off >>= 1) se += __shfl_xor_sync(0xffffffffu, se, off);
    if (j == 0) out[b] = mm + logf(se) - ts;
}

// ---------------- launch ----------------
extern "C" void kernel_launch(void* const* d_in, const int* in_sizes, int n_in,
                              void* d_out, int out_size) {
    const int*   sentences = (const int*)d_in[0];
    const int*   tags      = (const int*)d_in[1];
    const float* emb       = (const float*)d_in[2];
    const float* W_ih_f    = (const float*)d_in[3];
    const float* W_hh_f    = (const float*)d_in[4];
    const float* b_f       = (const float*)d_in[5];
    const float* W_ih_b    = (const float*)d_in[6];
    const float* W_hh_b    = (const float*)d_in[7];
    const float* b_b       = (const float*)d_in[8];
    const float* W_lin     = (const float*)d_in[9];
    const float* b_lin     = (const float*)d_in[10];
    const float* trans     = (const float*)d_in[11];
    float* out = (float*)d_out;

    int smem_ip = (HID * IP_ROWS + 2 * IP_CHF) * 4;                    // 102720 B
    int smem_rc = (HID * 152 + HID * RBS + 2 * 2432) * 4;              // 211456 B
    cudaFuncSetAttribute(k_inproj, cudaFuncAttributeMaxDynamicSharedMemorySize, smem_ip);
    cudaFuncSetAttribute(k_recur,  cudaFuncAttributeMaxDynamicSharedMemorySize, smem_rc);

    k_reset<<<1, 32>>>();
    k_gather<<<SEQ, 256>>>(sentences, emb);
    dim3 gip(IP_JS, IP_MB, 2);
    k_inproj<<<gip, IP_THREADS, smem_ip>>>(W_ih_f, b_f, W_ih_b, b_b);
    k_recur<<<2 * RBG * RUS, R_THREADS, smem_rc>>>(W_hh_f, W_hh_b);
    k_emit<<<SEQ, 256>>>(W_lin, b_lin);
    k_crf<<<NB, 32>>>(tags, trans, out);
}

// round 9
// speedup vs baseline: 1.8745x; 1.0331x over previous
#include <cuda_runtime.h>
#include <cstdint>
#include <math.h>

#define SEQ 256
#define NB 64
#define HID 300
#define G4 1200
#define NTAG 12

// recurrence: 2 dirs x 8 batch-groups x 8 unit-slices = 128 CTAs
#define RBG 8           // batch groups
#define RUS 8           // unit slices
#define RBS 8           // batch per group
#define RUPC 38         // units per slice (last slice has 34)
#define R_P 76          // row pairs (152 gate rows / 2)
#define R_KCH 75
#define R_THREADS 320   // 304 active = 4 ksplit x 76 rowpairs

// input projection: persistent weights; 7 seq-splits x 20 m x 2 dirs = 280 CTAs (one wave)
// s-blocked: 2 sequence positions per pass share each weight LDS
#define IP_MB 20
#define IP_ROWS 60
#define IP_THREADS 320
#define IP_JS 7         // CTAs sharing one weight tile (sequence split)
#define IP_SC 37        // s per CTA (last CTA: 34)
#define IP_KC 30        // k per chunk
#define IP_NKC 10       // chunks per s
#define IP_CHF (IP_KC * NB)       // 1920 floats per chunk
#define IP_CH4 (IP_CHF / 4)       // 480 float4 per chunk

typedef unsigned long long ull;

__device__ __forceinline__ ull pack2(float lo, float hi) {
    ull r; asm("mov.b64 %0, {%1, %2};" : "=l"(r) : "f"(lo), "f"(hi)); return r;
}
__device__ __forceinline__ void unpack2(ull v, float& lo, float& hi) {
    asm("mov.b64 {%0, %1}, %2;" : "=f"(lo), "=f"(hi) : "l"(v));
}
__device__ __forceinline__ ull fma2(ull a, ull b, ull c) {
    ull d; asm("fma.rn.f32x2 %0, %1, %2, %3;" : "=l"(d) : "l"(a), "l"(b), "l"(c)); return d;
}
__device__ __forceinline__ ull add2(ull a, ull b) {
    ull d; asm("add.rn.f32x2 %0, %1, %2;" : "=l"(d) : "l"(a), "l"(b)); return d;
}
__device__ __forceinline__ float ftanh(float x) {
    float y; asm("tanh.approx.f32 %0, %1;" : "=f"(y) : "f"(x)); return y;
}
__device__ __forceinline__ float fsigm(float x) {
    return 0.5f * ftanh(0.5f * x) + 0.5f;
}
__device__ __forceinline__ uint32_t smem_u32_of(const void* p) {
    uint32_t a;
    asm("{ .reg .u64 t0; cvta.to.shared.u64 t0, %1; cvt.u32.u64 %0, t0; }" : "=r"(a) : "l"(p));
    return a;
}
__device__ __forceinline__ void cpasync16(uint32_t saddr, const void* g) {
    asm volatile("cp.async.cg.shared.global [%0], [%1], 16;" :: "r"(saddr), "l"(g));
}

// ---------------- scratch (device globals; no allocations) ----------------
__device__ float g_XT[SEQ * HID * NB];             // x transposed: [s][k][b]
__device__ float g_G[2][SEQ][G4 * NB];             // input proj + bias: [d][s][row][b]
__device__ float g_hall[2][SEQ][RBG * HID * RBS];  // h: [d][s][group][u*8+bo]
__device__ float g_emit[SEQ][NB][NTAG];            // emissions
__device__ int   g_cnt2[16][32];                   // per (dir,group) counters, 128B-padded

extern __shared__ float sm[];

// ---------------- reset barrier counters ----------------
__global__ void k_reset() {
    if (threadIdx.x < 16) g_cnt2[threadIdx.x][0] = 0;
}

// ---------------- embedding gather + transpose ----------------
__global__ void k_gather(const int* __restrict__ sent, const float* __restrict__ emb) {
    int s = blockIdx.x;
    __shared__ float sx[64][33];
    __shared__ int rows[64];
    int t = threadIdx.x;  // 256
    if (t < 64) rows[t] = sent[t * SEQ + s];
    __syncthreads();
    for (int kc = 0; kc < 10; kc++) {
        int kbase = kc * 32;
        int width = HID - kbase; if (width > 32) width = 32;
        int kk = t & 31, bg = t >> 5;
        if (kk < width) {
            for (int b = bg; b < 64; b += 8)
                sx[b][kk] = emb[rows[b] * HID + kbase + kk];
        }
        __syncthreads();
        int b = t & 63, kg = t >> 6;
        for (int k2 = kg; k2 < width; k2 += 4)
            g_XT[(s * HID + kbase + k2) * NB + b] = sx[b][k2];
        __syncthreads();
    }
}

// ---------------- input projection: persistent weights, s-blocked (2 s per pass) ----------------
// CTA = (j, m, d): 60 gate rows; s in [j*37, ...) processed in pairs so each weight
// LDS feeds 2 sequence positions. x streamed via cp.async double buffering.
__global__ void __launch_bounds__(IP_THREADS, 2) k_inproj(
    const float* __restrict__ Wf, const float* __restrict__ bf,
    const float* __restrict__ Wb, const float* __restrict__ bb)
{
    int j = blockIdx.x, m = blockIdx.y, d = blockIdx.z;
    const float* W    = d ? Wb : Wf;
    const float* bias = d ? bb : bf;
    float* ws  = sm;                     // 18000 floats: ws[k*60 + r]
    float* xa0 = sm + HID * IP_ROWS;     // 1920 floats (stream A, buf 0)
    float* xb0 = xa0 + IP_CHF;           // 1920 floats (stream B, buf 0)
    float* xa1 = xb0 + IP_CHF;           // buf 1
    float* xb1 = xa1 + IP_CHF;
    int t = threadIdx.x;
    int u0 = m * 15;

    int s0 = j * IP_SC;
    int ns = SEQ - s0; if (ns > IP_SC) ns = IP_SC;
    int npairs = (ns + 1) >> 1;
    int slast = s0 + ns - 1;

    uint32_t xa0a = smem_u32_of(xa0), xb0a = smem_u32_of(xb0);
    uint32_t xa1a = smem_u32_of(xa1), xb1a = smem_u32_of(xb1);

    // stage weights once: ws[k*60 + r], r = ul*4 + gate, row = gate*300 + u0 + ul
    for (int idx = t; idx < HID * IP_ROWS; idx += IP_THREADS) {
        int k = idx / IP_ROWS, r = idx - k * IP_ROWS;
        int ul = r >> 2, gate = r & 3;
        ws[idx] = W[(gate * HID + u0 + ul) * HID + k];
    }

    int b = t & 63, rg = t >> 6;   // rg 0..4, owns rows rg*12 .. rg*12+11

    // cache bias + output rows for this thread
    float bv[12];
    int rowv[12];
#pragma unroll
    for (int q = 0; q < 12; q++) {
        int r = rg * 12 + q;
        int row = (r & 3) * HID + u0 + (r >> 2);
        rowv[q] = row;
        bv[q] = bias[row];
    }
    __syncthreads();   // ws ready

    for (int pr = 0; pr < npairs; pr++) {
        int sA = s0 + 2 * pr;
        int sB = sA + 1; if (sB > slast) sB = sA;   // duplicate on odd remainder
        const float4* gA = (const float4*)(g_XT + (long long)sA * (HID * NB));
        const float4* gB = (const float4*)(g_XT + (long long)sB * (HID * NB));

        // prefetch chunk 0 of both streams (960 float4, 3 per thread)
#pragma unroll
        for (int q = 0; q < 3; q++) {
            int gi = t + q * IP_THREADS;
            bool isA = gi < IP_CH4;
            uint32_t dst = isA ? (xa0a + gi * 16) : (xb0a + (gi - IP_CH4) * 16);
            const float4* src = isA ? (gA + gi) : (gB + (gi - IP_CH4));
            cpasync16(dst, src);
        }
        asm volatile("cp.async.commit_group;");

        ull accA[6], accB[6];
#pragma unroll
        for (int p = 0; p < 6; p++) { accA[p] = 0ull; accB[p] = 0ull; }

        const ulonglong2* wp = ((const ulonglong2*)ws) + rg * 3;

        for (int kc = 0; kc < IP_NKC; kc++) {
            if (kc < IP_NKC - 1) {
                int nb4 = (kc + 1) * IP_CH4;
                uint32_t da = ((kc + 1) & 1) ? xa1a : xa0a;
                uint32_t db = ((kc + 1) & 1) ? xb1a : xb0a;
#pragma unroll
                for (int q = 0; q < 3; q++) {
                    int gi = t + q * IP_THREADS;
                    bool isA = gi < IP_CH4;
                    uint32_t dst = isA ? (da + gi * 16) : (db + (gi - IP_CH4) * 16);
                    const float4* src = isA ? (gA + nb4 + gi) : (gB + nb4 + (gi - IP_CH4));
                    cpasync16(dst, src);
                }
                asm volatile("cp.async.commit_group;");
                asm volatile("cp.async.wait_group 1;");
            } else {
                asm volatile("cp.async.wait_group 0;");
            }
            __syncthreads();   // current chunk visible

            const float* xpA = ((kc & 1) ? xa1 : xa0) + b;
            const float* xpB = ((kc & 1) ? xb1 : xb0) + b;
#pragma unroll 5
            for (int k = 0; k < IP_KC; k++) {
                float xa = xpA[k * NB];
                float xb = xpB[k * NB];
                ull h2a = pack2(xa, xa);
                ull h2b = pack2(xb, xb);
                ulonglong2 w0 = wp[0], w1 = wp[1], w2 = wp[2];
                accA[0] = fma2(w0.x, h2a, accA[0]);  accB[0] = fma2(w0.x, h2b, accB[0]);
                accA[1] = fma2(w0.y, h2a, accA[1]);  accB[1] = fma2(w0.y, h2b, accB[1]);
                accA[2] = fma2(w1.x, h2a, accA[2]);  accB[2] = fma2(w1.x, h2b, accB[2]);
                accA[3] = fma2(w1.y, h2a, accA[3]);  accB[3] = fma2(w1.y, h2b, accB[3]);
                accA[4] = fma2(w2.x, h2a, accA[4]);  accB[4] = fma2(w2.x, h2b, accB[4]);
                accA[5] = fma2(w2.y, h2a, accA[5]);  accB[5] = fma2(w2.y, h2b, accB[5]);
                wp += 15;  // 60 floats per k
            }
            __syncthreads();   // reads done before this buffer is refilled
        }

        // store G for sA and sB
        float* GdA = g_G[d][sA];
        float* GdB = g_G[d][sB];
#pragma unroll
        for (int p = 0; p < 6; p++) {
            float a0, a1, b0, b1;
            unpack2(accA[p], a0, a1);
            unpack2(accB[p], b0, b1);
            int ra = rowv[2 * p], rb = rowv[2 * p + 1];
            GdA[ra * NB + b] = a0 + bv[2 * p];
            GdA[rb * NB + b] = a1 + bv[2 * p + 1];
            GdB[ra * NB + b] = b0 + bv[2 * p];
            GdB[rb * NB + b] = b1 + bv[2 * p + 1];
        }
    }
}

// ---------------- persistent LSTM recurrence, 2D (batch-group x unit-slice) ----------------
__global__ void __launch_bounds__(R_THREADS, 1) k_recur(
    const float* __restrict__ Whf, const float* __restrict__ Whb)
{
    int bid = blockIdx.x;
    int d = bid >> 6;
    int g = (bid >> 3) & 7;
    int m = bid & 7;
    const float* W = d ? Whb : Whf;

    float* ws = sm;                    // ws[k*152 + r], r = ul*4+gate (row pairs packed)
    float* hs = sm + HID * 152;        // hs[k*8 + bo]
    ull*  red = (ull*)(hs + HID * RBS);

    int t = threadIdx.x;
    int u0 = m * RUPC;
    int cu = HID - u0; if (cu > RUPC) cu = RUPC;

    for (int idx = t; idx < HID * 152; idx += R_THREADS) {
        int k = idx / 152, r = idx - k * 152;
        int ul = r >> 2, gate = r & 3;
        ws[idx] = (ul < cu) ? W[(gate * HID + u0 + ul) * HID + k] : 0.f;
    }
    __syncthreads();

    int ks = t / R_P;          // 0..3 active, 4 = spare
    int p  = t - ks * R_P;     // rowpair 0..75
    int k0 = (ks & 3) * R_KCH;
    int bp = (ks > 3) ? 3 : ks;        // batch-pair
    int ul = p >> 1;
    bool doer = (t < 304) && ((p & 1) == 0) && (ul < cu);
    int boff = g * RBS + bp * 2;
    float c0 = 0.f, c1 = 0.f;
    int* cnt = &g_cnt2[d * 8 + g][0];
    const ull* wsu = (const ull*)ws;
    const ulonglong2* hsu = (const ulonglong2*)hs;

    for (int step = 0; step < SEQ; step++) {
        int pos = d ? (SEQ - 1 - step) : step;
        const float* Gp = g_G[d][pos];

        float2 Gv0, Gv1, Gv2, Gv3;
        if (doer) {
            int gb = (u0 + ul) * NB + boff;
            Gv0 = *(const float2*)(Gp + 0 * HID * NB + gb);
            Gv1 = *(const float2*)(Gp + 1 * HID * NB + gb);
            Gv2 = *(const float2*)(Gp + 2 * HID * NB + gb);
            Gv3 = *(const float2*)(Gp + 3 * HID * NB + gb);
        }

        float s0lo = 0.f, s0hi = 0.f, s1lo = 0.f, s1hi = 0.f;

        if (step > 0) {
            if (t == 0) {
                int target = RUS * step;
                int v;
                do {
                    asm volatile("ld.acquire.gpu.global.b32 %0, [%1];" : "=r"(v) : "l"(cnt) : "memory");
                    if (v < target) __nanosleep(20);
                } while (v < target);
            }
            __syncthreads();

            {
                int prev = d ? (SEQ - step) : (step - 1);
                const float4* src = (const float4*)(g_hall[d][prev] + g * (HID * RBS));
                float4* dst = (float4*)hs;
                for (int idx = t; idx < HID * RBS / 4; idx += R_THREADS) dst[idx] = src[idx];
            }
            __syncthreads();

            ull a00 = 0, a01 = 0, a02 = 0, a03 = 0;
            ull a10 = 0, a11 = 0, a12 = 0, a13 = 0;
#pragma unroll 5
            for (int kk = 0; kk < R_KCH; kk++) {
                int k = k0 + kk;
                ull w = wsu[k * R_P + p];
                float w0, w1; unpack2(w, w0, w1);
                ull w00 = pack2(w0, w0), w11 = pack2(w1, w1);
                ulonglong2 hA = hsu[k * 2];
                ulonglong2 hB = hsu[k * 2 + 1];
                a00 = fma2(w00, hA.x, a00); a01 = fma2(w00, hA.y, a01);
                a02 = fma2(w00, hB.x, a02); a03 = fma2(w00, hB.y, a03);
                a10 = fma2(w11, hA.x, a10); a11 = fma2(w11, hA.y, a11);
                a12 = fma2(w11, hB.x, a12); a13 = fma2(w11, hB.y, a13);
            }
            if (t < 304) {
                int base = p * 32 + ks;
                red[base + 0 * 8 + 0] = a00; red[base + 1 * 8 + 0] = a01;
                red[base + 2 * 8 + 0] = a02; red[base + 3 * 8 + 0] = a03;
                red[base + 0 * 8 + 4] = a10; red[base + 1 * 8 + 4] = a11;
                red[base + 2 * 8 + 4] = a12; red[base + 3 * 8 + 4] = a13;
            }
            __syncthreads();

            {
                const ulonglong2* r2 = (const ulonglong2*)red;
                int ib = (p * 8 + bp * 2) * 2;
                ulonglong2 q0 = r2[ib + 0], q1 = r2[ib + 1];
                ulonglong2 q2 = r2[ib + 2], q3 = r2[ib + 3];
                ull s0 = add2(add2(q0.x, q0.y), add2(q1.x, q1.y));
                ull s1 = add2(add2(q2.x, q2.y), add2(q3.x, q3.y));
                unpack2(s0, s0lo, s0hi);
                unpack2(s1, s1lo, s1hi);
            }
        }

        float g2lo = __shfl_down_sync(0xffffffffu, s0lo, 1);
        float g2hi = __shfl_down_sync(0xffffffffu, s0hi, 1);
        float g3lo = __shfl_down_sync(0xffffffffu, s1lo, 1);
        float g3hi = __shfl_down_sync(0xffffffffu, s1hi, 1);

        if (doer) {
            float i0 = fsigm(s0lo + Gv0.x), i1 = fsigm(s0hi + Gv0.y);
            float f0 = fsigm(s1lo + Gv1.x), f1 = fsigm(s1hi + Gv1.y);
            float q0 = ftanh(g2lo + Gv2.x), q1 = ftanh(g2hi + Gv2.y);
            float o0 = fsigm(g3lo + Gv3.x), o1 = fsigm(g3hi + Gv3.y);
            c0 = f0 * c0 + i0 * q0;
            c1 = f1 * c1 + i1 * q1;
            float2 hv;
            hv.x = o0 * ftanh(c0);
            hv.y = o1 * ftanh(c1);
            *(float2*)(g_hall[d][pos] + g * (HID * RBS) + (u0 + ul) * RBS + bp * 2) = hv;
        }

        __syncthreads();
        if (t == 0)
            asm volatile("red.release.gpu.global.add.s32 [%0], 1;" :: "l"(cnt) : "memory");
    }
}

// ---------------- emissions: emit[s][b][j] = W_lin @ [h_f; h_b] + b_lin ----------------
__global__ void k_emit(const float* __restrict__ Wl, const float* __restrict__ bl) {
    int s = blockIdx.x, t = threadIdx.x;  // 256
    __shared__ float wl[600 * NTAG];
    __shared__ float red2[4 * NTAG * NB];
    for (int idx = t; idx < 600 * NTAG; idx += 256) {
        int k = idx / NTAG, j = idx - k * NTAG;
        wl[idx] = Wl[j * 600 + k];
    }
    __syncthreads();
    int b = t & 63, ksx = t >> 6;
    int gof = (b >> 3) * (HID * RBS) + (b & 7);
    float acc[NTAG];
#pragma unroll
    for (int j = 0; j < NTAG; j++) acc[j] = 0.f;
    const float* hf = g_hall[0][s];
    const float* hb = g_hall[1][s];
    int k0 = ksx * 150;
    for (int k = k0; k < k0 + 150; k++) {
        float v = (k < HID) ? hf[gof + k * RBS] : hb[gof + (k - HID) * RBS];
        const float4* w4 = (const float4*)(wl + k * NTAG);
#pragma unroll
        for (int q = 0; q < 3; q++) {
            float4 w = w4[q];
            acc[4 * q + 0] += w.x * v; acc[4 * q + 1] += w.y * v;
            acc[4 * q + 2] += w.z * v; acc[4 * q + 3] += w.w * v;
        }
    }
#pragma unroll
    for (int j = 0; j < NTAG; j++) red2[(ksx * NTAG + j) * NB + b] = acc[j];
    __syncthreads();
    for (int idx = t; idx < NTAG * NB; idx += 256) {
        int j = idx >> 6, b2 = idx & 63;
        float v = red2[(0 * NTAG + j) * NB + b2] + red2[(1 * NTAG + j) * NB + b2]
                + red2[(2 * NTAG + j) * NB + b2] + red2[(3 * NTAG + j) * NB + b2];
        g_emit[s][b2][j] = v + bl[j];
    }
}

// ---------------- CRF forward + gold score + loss (one warp per batch) ----------------
__global__ void k_crf(const int* __restrict__ tags, const float* __restrict__ trans,
                      float* __restrict__ out) {
    int b = blockIdx.x;
    int j = threadIdx.x;
    float Tcol[NTAG];
#pragma unroll
    for (int i = 0; i < NTAG; i++) Tcol[i] = (j < NTAG) ? trans[i * NTAG + j] : 0.f;
    float dcur = (j < NTAG) ? g_emit[0][b][j] : -1e30f;

    float ts = 0.f;
    for (int s = j; s < SEQ; s += 32) {
        int tg = tags[b * SEQ + s];
        ts += g_emit[s][b][tg];
        if (s < SEQ - 1) ts += trans[tg * NTAG + tags[b * SEQ + s + 1]];
    }
#pragma unroll
    for (int off = 16; off; off >>= 1) ts += __shfl_xor_sync(0xffffffffu, ts, off);

    for (int s = 1; s < SEQ; s++) {
        float v[NTAG];
#pragma unroll
        for (int i = 0; i < NTAG; i++)
            v[i] = __shfl_sync(0xffffffffu, dcur, i) + Tcol[i];
        float mx = v[0];
#pragma unroll
        for (int i = 1; i < NTAG; i++) mx = fmaxf(mx, v[i]);
        float sum = 0.f;
#pragma unroll
        for (int i = 0; i < NTAG; i++) sum += expf(v[i] - mx);
        float e = (j < NTAG) ? g_emit[s][b][j] : 0.f;
        dcur = e + mx + logf(sum);
    }

    float dd = (j < NTAG) ? dcur : -1e30f;
    float mm = dd;
#pragma unroll
    for (int off = 16; off; off >>= 1) mm = fmaxf(mm, __shfl_xor_sync(0xffffffffu, mm, off));
    float se = (j < NTAG) ? expf(dd - mm) : 0.f;
#pragma unroll
    for (int off = 16; off; off >>= 1) se += __shfl_xor_sync(0xffffffffu, se, off);
    if (j == 0) out[b] = mm + logf(se) - ts;
}

// ---------------- launch ----------------
extern "C" void kernel_launch(void* const* d_in, const int* in_sizes, int n_in,
                              void* d_out, int out_size) {
    const int*   sentences = (const int*)d_in[0];
    const int*   tags      = (const int*)d_in[1];
    const float* emb       = (const float*)d_in[2];
    const float* W_ih_f    = (const float*)d_in[3];
    const float* W_hh_f    = (const float*)d_in[4];
    const float* b_f       = (const float*)d_in[5];
    const float* W_ih_b    = (const float*)d_in[6];
    const float* W_hh_b    = (const float*)d_in[7];
    const float* b_b       = (const float*)d_in[8];
    const float* W_lin     = (const float*)d_in[9];
    const float* b_lin     = (const float*)d_in[10];
    const float* trans     = (const float*)d_in[11];
    float* out = (float*)d_out;

    int smem_ip = (HID * IP_ROWS + 4 * IP_CHF) * 4;                    // 102720 B
    int smem_rc = (HID * 152 + HID * RBS + 2 * 2432) * 4;              // 211456 B
    cudaFuncSetAttribute(k_inproj, cudaFuncAttributeMaxDynamicSharedMemorySize, smem_ip);
    cudaFuncSetAttribute(k_recur,  cudaFuncAttributeMaxDynamicSharedMemorySize, smem_rc);

    k_reset<<<1, 32>>>();
    k_gather<<<SEQ, 256>>>(sentences, emb);
    dim3 gip(IP_JS, IP_MB, 2);
    k_inproj<<<gip, IP_THREADS, smem_ip>>>(W_ih_f, b_f, W_ih_b, b_b);
    k_recur<<<2 * RBG * RUS, R_THREADS, smem_rc>>>(W_hh_f, W_hh_b);
    k_emit<<<SEQ, 256>>>(W_lin, b_lin);
    k_crf<<<NB, 32>>>(tags, trans, out);
}

// round 10
// speedup vs baseline: 2.4163x; 1.2891x over previous
#include <cuda_runtime.h>
#include <cstdint>
#include <math.h>

#define SEQ 256
#define NB 64
#define HID 300
#define G4 1200
#define NTAG 12

// recurrence: 2 dirs x 8 batch-groups x 8 unit-slices = 128 CTAs
#define RBG 8           // batch groups
#define RUS 8           // unit slices
#define RBS 8           // batch per group
#define RUPC 38         // units per slice (last slice has 34)
#define R_P 76          // row pairs (152 gate rows / 2)
#define R_KS 8          // k splits
#define R_ACT 608       // active GEMV threads = 8 * 76
#define R_THREADS 640

// input projection: persistent weights; 7 seq-splits x 20 m x 2 dirs = 280 CTAs (one wave)
#define IP_MB 20
#define IP_ROWS 60
#define IP_THREADS 320
#define IP_JS 7
#define IP_SC 37
#define IP_KC 30
#define IP_NKC 10
#define IP_CHF (IP_KC * NB)
#define IP_CH4 (IP_CHF / 4)

typedef unsigned long long ull;

__device__ __forceinline__ ull pack2(float lo, float hi) {
    ull r; asm("mov.b64 %0, {%1, %2};" : "=l"(r) : "f"(lo), "f"(hi)); return r;
}
__device__ __forceinline__ void unpack2(ull v, float& lo, float& hi) {
    asm("mov.b64 {%0, %1}, %2;" : "=f"(lo), "=f"(hi) : "l"(v));
}
__device__ __forceinline__ ull fma2(ull a, ull b, ull c) {
    ull d; asm("fma.rn.f32x2 %0, %1, %2, %3;" : "=l"(d) : "l"(a), "l"(b), "l"(c)); return d;
}
__device__ __forceinline__ ull add2(ull a, ull b) {
    ull d; asm("add.rn.f32x2 %0, %1, %2;" : "=l"(d) : "l"(a), "l"(b)); return d;
}
__device__ __forceinline__ float ftanh(float x) {
    float y; asm("tanh.approx.f32 %0, %1;" : "=f"(y) : "f"(x)); return y;
}
__device__ __forceinline__ float fsigm(float x) {
    return 0.5f * ftanh(0.5f * x) + 0.5f;
}
__device__ __forceinline__ uint32_t smem_u32_of(const void* p) {
    uint32_t a;
    asm("{ .reg .u64 t0; cvta.to.shared.u64 t0, %1; cvt.u32.u64 %0, t0; }" : "=r"(a) : "l"(p));
    return a;
}
__device__ __forceinline__ void cpasync16(uint32_t saddr, const void* g) {
    asm volatile("cp.async.cg.shared.global [%0], [%1], 16;" :: "r"(saddr), "l"(g));
}

// ---------------- scratch (device globals; no allocations) ----------------
__device__ float g_XT[SEQ * HID * NB];
__device__ float g_G[2][SEQ][G4 * NB];
__device__ float g_hall[2][SEQ][RBG * HID * RBS];
__device__ float g_emit[SEQ][NB][NTAG];
__device__ int   g_cnt2[16][32];

extern __shared__ float sm[];

// ---------------- reset barrier counters ----------------
__global__ void k_reset() {
    if (threadIdx.x < 16) g_cnt2[threadIdx.x][0] = 0;
}

// ---------------- embedding gather + transpose ----------------
__global__ void k_gather(const int* __restrict__ sent, const float* __restrict__ emb) {
    int s = blockIdx.x;
    __shared__ float sx[64][33];
    __shared__ int rows[64];
    int t = threadIdx.x;  // 256
    if (t < 64) rows[t] = sent[t * SEQ + s];
    __syncthreads();
    for (int kc = 0; kc < 10; kc++) {
        int kbase = kc * 32;
        int width = HID - kbase; if (width > 32) width = 32;
        int kk = t & 31, bg = t >> 5;
        if (kk < width) {
            for (int b = bg; b < 64; b += 8)
                sx[b][kk] = emb[rows[b] * HID + kbase + kk];
        }
        __syncthreads();
        int b = t & 63, kg = t >> 6;
        for (int k2 = kg; k2 < width; k2 += 4)
            g_XT[(s * HID + kbase + k2) * NB + b] = sx[b][k2];
        __syncthreads();
    }
}

// ---------------- input projection: persistent weights, s-blocked (2 s per pass) ----------------
__global__ void __launch_bounds__(IP_THREADS, 2) k_inproj(
    const float* __restrict__ Wf, const float* __restrict__ bf,
    const float* __restrict__ Wb, const float* __restrict__ bb)
{
    int j = blockIdx.x, m = blockIdx.y, d = blockIdx.z;
    const float* W    = d ? Wb : Wf;
    const float* bias = d ? bb : bf;
    float* ws  = sm;
    float* xa0 = sm + HID * IP_ROWS;
    float* xb0 = xa0 + IP_CHF;
    float* xa1 = xb0 + IP_CHF;
    float* xb1 = xa1 + IP_CHF;
    int t = threadIdx.x;
    int u0 = m * 15;

    int s0 = j * IP_SC;
    int ns = SEQ - s0; if (ns > IP_SC) ns = IP_SC;
    int npairs = (ns + 1) >> 1;
    int slast = s0 + ns - 1;

    uint32_t xa0a = smem_u32_of(xa0), xb0a = smem_u32_of(xb0);
    uint32_t xa1a = smem_u32_of(xa1), xb1a = smem_u32_of(xb1);

    for (int idx = t; idx < HID * IP_ROWS; idx += IP_THREADS) {
        int k = idx / IP_ROWS, r = idx - k * IP_ROWS;
        int ul = r >> 2, gate = r & 3;
        ws[idx] = W[(gate * HID + u0 + ul) * HID + k];
    }

    int b = t & 63, rg = t >> 6;

    float bv[12];
    int rowv[12];
#pragma unroll
    for (int q = 0; q < 12; q++) {
        int r = rg * 12 + q;
        int row = (r & 3) * HID + u0 + (r >> 2);
        rowv[q] = row;
        bv[q] = bias[row];
    }
    __syncthreads();

    for (int pr = 0; pr < npairs; pr++) {
        int sA = s0 + 2 * pr;
        int sB = sA + 1; if (sB > slast) sB = sA;
        const float4* gA = (const float4*)(g_XT + (long long)sA * (HID * NB));
        const float4* gB = (const float4*)(g_XT + (long long)sB * (HID * NB));

#pragma unroll
        for (int q = 0; q < 3; q++) {
            int gi = t + q * IP_THREADS;
            bool isA = gi < IP_CH4;
            uint32_t dst = isA ? (xa0a + gi * 16) : (xb0a + (gi - IP_CH4) * 16);
            const float4* src = isA ? (gA + gi) : (gB + (gi - IP_CH4));
            cpasync16(dst, src);
        }
        asm volatile("cp.async.commit_group;");

        ull accA[6], accB[6];
#pragma unroll
        for (int p = 0; p < 6; p++) { accA[p] = 0ull; accB[p] = 0ull; }

        const ulonglong2* wp = ((const ulonglong2*)ws) + rg * 3;

        for (int kc = 0; kc < IP_NKC; kc++) {
            if (kc < IP_NKC - 1) {
                int nb4 = (kc + 1) * IP_CH4;
                uint32_t da = ((kc + 1) & 1) ? xa1a : xa0a;
                uint32_t db = ((kc + 1) & 1) ? xb1a : xb0a;
#pragma unroll
                for (int q = 0; q < 3; q++) {
                    int gi = t + q * IP_THREADS;
                    bool isA = gi < IP_CH4;
                    uint32_t dst = isA ? (da + gi * 16) : (db + (gi - IP_CH4) * 16);
                    const float4* src = isA ? (gA + nb4 + gi) : (gB + nb4 + (gi - IP_CH4));
                    cpasync16(dst, src);
                }
                asm volatile("cp.async.commit_group;");
                asm volatile("cp.async.wait_group 1;");
            } else {
                asm volatile("cp.async.wait_group 0;");
            }
            __syncthreads();

            const float* xpA = ((kc & 1) ? xa1 : xa0) + b;
            const float* xpB = ((kc & 1) ? xb1 : xb0) + b;
#pragma unroll 5
            for (int k = 0; k < IP_KC; k++) {
                float xa = xpA[k * NB];
                float xb = xpB[k * NB];
                ull h2a = pack2(xa, xa);
                ull h2b = pack2(xb, xb);
                ulonglong2 w0 = wp[0], w1 = wp[1], w2 = wp[2];
                accA[0] = fma2(w0.x, h2a, accA[0]);  accB[0] = fma2(w0.x, h2b, accB[0]);
                accA[1] = fma2(w0.y, h2a, accA[1]);  accB[1] = fma2(w0.y, h2b, accB[1]);
                accA[2] = fma2(w1.x, h2a, accA[2]);  accB[2] = fma2(w1.x, h2b, accB[2]);
                accA[3] = fma2(w1.y, h2a, accA[3]);  accB[3] = fma2(w1.y, h2b, accB[3]);
                accA[4] = fma2(w2.x, h2a, accA[4]);  accB[4] = fma2(w2.x, h2b, accB[4]);
                accA[5] = fma2(w2.y, h2a, accA[5]);  accB[5] = fma2(w2.y, h2b, accB[5]);
                wp += 15;
            }
            __syncthreads();
        }

        float* GdA = g_G[d][sA];
        float* GdB = g_G[d][sB];
#pragma unroll
        for (int p = 0; p < 6; p++) {
            float a0, a1, b0, b1;
            unpack2(accA[p], a0, a1);
            unpack2(accB[p], b0, b1);
            int ra = rowv[2 * p], rb = rowv[2 * p + 1];
            GdA[ra * NB + b] = a0 + bv[2 * p];
            GdA[rb * NB + b] = a1 + bv[2 * p + 1];
            GdB[ra * NB + b] = b0 + bv[2 * p];
            GdB[rb * NB + b] = b1 + bv[2 * p + 1];
        }
    }
}

// ---------------- persistent LSTM recurrence: 640 threads, 8-way k-split ----------------
// CTA = (d, g, m). Owns units [m*38, m*38+cu) x batches [g*8, g*8+8).
// smem: ws 45600 f | hs 2400 f | red 4864 ull (layout red[j*608 + t], conflict-free)
__global__ void __launch_bounds__(R_THREADS, 1) k_recur(
    const float* __restrict__ Whf, const float* __restrict__ Whb)
{
    int bid = blockIdx.x;
    int d = bid >> 6;
    int g = (bid >> 3) & 7;
    int m = bid & 7;
    const float* W = d ? Whb : Whf;

    float* ws = sm;                    // ws[k*152 + r], row pairs packed as ull
    float* hs = sm + HID * 152;        // hs[k*8 + bo]
    ull*  red = (ull*)(hs + HID * RBS);   // 8 * 608 ull

    int t = threadIdx.x;
    int u0 = m * RUPC;
    int cu = HID - u0; if (cu > RUPC) cu = RUPC;

    for (int idx = t; idx < HID * 152; idx += R_THREADS) {
        int k = idx / 152, r = idx - k * 152;
        int ul = r >> 2, gate = r & 3;
        ws[idx] = (ul < cu) ? W[(gate * HID + u0 + ul) * HID + k] : 0.f;
    }
    __syncthreads();

    int ks = t / R_P;                  // 0..7 active, 8 = spare warp
    int p  = t - ks * R_P;             // rowpair 0..75
    bool gemv = (t < R_ACT);
    int k0   = (ks < 4) ? 38 * ks : 152 + 37 * (ks - 4);
    int klen = (ks < 4) ? 38 : 37;
    if (!gemv) { k0 = 0; klen = 0; }
    int bp = (t < 304) ? ks : 0;       // phase2 batch-pair (= ks for t<304)
    int ul = p >> 1;
    bool doer = (t < 304) && ((p & 1) == 0) && (ul < cu);
    int boff = g * RBS + bp * 2;
    float c0 = 0.f, c1 = 0.f;
    int* cnt = &g_cnt2[d * 8 + g][0];
    const ull* wsu = (const ull*)ws;
    const ulonglong2* hsu = (const ulonglong2*)hs;

    for (int step = 0; step < SEQ; step++) {
        int pos = d ? (SEQ - 1 - step) : step;
        const float* Gp = g_G[d][pos];

        float2 Gv0, Gv1, Gv2, Gv3;
        if (doer) {
            int gb = (u0 + ul) * NB + boff;
            Gv0 = *(const float2*)(Gp + 0 * HID * NB + gb);
            Gv1 = *(const float2*)(Gp + 1 * HID * NB + gb);
            Gv2 = *(const float2*)(Gp + 2 * HID * NB + gb);
            Gv3 = *(const float2*)(Gp + 3 * HID * NB + gb);
        }

        float s0lo = 0.f, s0hi = 0.f, s1lo = 0.f, s1hi = 0.f;

        if (step > 0) {
            if (t == 0) {
                int target = RUS * step;
                int v;
                do {
                    asm volatile("ld.acquire.gpu.global.b32 %0, [%1];" : "=r"(v) : "l"(cnt) : "memory");
                    if (v < target) __nanosleep(20);
                } while (v < target);
            }
            __syncthreads();

            {
                int prev = d ? (SEQ - step) : (step - 1);
                const float4* src = (const float4*)(g_hall[d][prev] + g * (HID * RBS));
                float4* dst = (float4*)hs;
                if (t < HID * RBS / 4) dst[t] = src[t];
            }
            __syncthreads();

            // partial GEMV: 2 rows x 8 batches per thread over klen k's
            ull a00 = 0, a01 = 0, a02 = 0, a03 = 0;
            ull a10 = 0, a11 = 0, a12 = 0, a13 = 0;
#pragma unroll 2
            for (int kk = 0; kk < klen; kk++) {
                int k = k0 + kk;
                ull w = wsu[k * R_P + p];
                float w0, w1; unpack2(w, w0, w1);
                ull w00 = pack2(w0, w0), w11 = pack2(w1, w1);
                ulonglong2 hA = hsu[k * 2];
                ulonglong2 hB = hsu[k * 2 + 1];
                a00 = fma2(w00, hA.x, a00); a01 = fma2(w00, hA.y, a01);
                a02 = fma2(w00, hB.x, a02); a03 = fma2(w00, hB.y, a03);
                a10 = fma2(w11, hA.x, a10); a11 = fma2(w11, hA.y, a11);
                a12 = fma2(w11, hB.x, a12); a13 = fma2(w11, hB.y, a13);
            }
            if (gemv) {
                // red[j*608 + t], j = r*4 + batchpair  (8B lane stride: conflict-free)
                red[0 * R_ACT + t] = a00; red[1 * R_ACT + t] = a01;
                red[2 * R_ACT + t] = a02; red[3 * R_ACT + t] = a03;
                red[4 * R_ACT + t] = a10; red[5 * R_ACT + t] = a11;
                red[6 * R_ACT + t] = a12; red[7 * R_ACT + t] = a13;
            }
            __syncthreads();

            // phase2: thread (p, bp) sums 8 k-splits for rows 2p,2p+1, batches 2bp,2bp+1
            if (t < 304) {
                const ull* r0 = red + bp * R_ACT + p;
                const ull* r1 = red + (4 + bp) * R_ACT + p;
                ull s0 = r0[0];
                ull s1 = r1[0];
#pragma unroll
                for (int q = 1; q < R_KS; q++) {
                    s0 = add2(s0, r0[q * R_P]);
                    s1 = add2(s1, r1[q * R_P]);
                }
                unpack2(s0, s0lo, s0hi);
                unpack2(s1, s1lo, s1hi);
            }
        }

        // exchange: even-p thread (gates i,f) pulls gates g,o from odd partner (t+1)
        float g2lo = __shfl_down_sync(0xffffffffu, s0lo, 1);
        float g2hi = __shfl_down_sync(0xffffffffu, s0hi, 1);
        float g3lo = __shfl_down_sync(0xffffffffu, s1lo, 1);
        float g3hi = __shfl_down_sync(0xffffffffu, s1hi, 1);

        if (doer) {
            float i0 = fsigm(s0lo + Gv0.x), i1 = fsigm(s0hi + Gv0.y);
            float f0 = fsigm(s1lo + Gv1.x), f1 = fsigm(s1hi + Gv1.y);
            float q0 = ftanh(g2lo + Gv2.x), q1 = ftanh(g2hi + Gv2.y);
            float o0 = fsigm(g3lo + Gv3.x), o1 = fsigm(g3hi + Gv3.y);
            c0 = f0 * c0 + i0 * q0;
            c1 = f1 * c1 + i1 * q1;
            float2 hv;
            hv.x = o0 * ftanh(c0);
            hv.y = o1 * ftanh(c1);
            *(float2*)(g_hall[d][pos] + g * (HID * RBS) + (u0 + ul) * RBS + bp * 2) = hv;
        }

        __syncthreads();
        if (t == 0)
            asm volatile("red.release.gpu.global.add.s32 [%0], 1;" :: "l"(cnt) : "memory");
    }
}

// ---------------- emissions ----------------
__global__ void k_emit(const float* __restrict__ Wl, const float* __restrict__ bl) {
    int s = blockIdx.x, t = threadIdx.x;  // 256
    __shared__ float wl[600 * NTAG];
    __shared__ float red2[4 * NTAG * NB];
    for (int idx = t; idx < 600 * NTAG; idx += 256) {
        int k = idx / NTAG, j = idx - k * NTAG;
        wl[idx] = Wl[j * 600 + k];
    }
    __syncthreads();
    int b = t & 63, ksx = t >> 6;
    int gof = (b >> 3) * (HID * RBS) + (b & 7);
    float acc[NTAG];
#pragma unroll
    for (int j = 0; j < NTAG; j++) acc[j] = 0.f;
    const float* hf = g_hall[0][s];
    const float* hb = g_hall[1][s];
    int k0 = ksx * 150;
    for (int k = k0; k < k0 + 150; k++) {
        float v = (k < HID) ? hf[gof + k * RBS] : hb[gof + (k - HID) * RBS];
        const float4* w4 = (const float4*)(wl + k * NTAG);
#pragma unroll
        for (int q = 0; q < 3; q++) {
            float4 w = w4[q];
            acc[4 * q + 0] += w.x * v; acc[4 * q + 1] += w.y * v;
            acc[4 * q + 2] += w.z * v; acc[4 * q + 3] += w.w * v;
        }
    }
#pragma unroll
    for (int j = 0; j < NTAG; j++) red2[(ksx * NTAG + j) * NB + b] = acc[j];
    __syncthreads();
    for (int idx = t; idx < NTAG * NB; idx += 256) {
        int j = idx >> 6, b2 = idx & 63;
        float v = red2[(0 * NTAG + j) * NB + b2] + red2[(1 * NTAG + j) * NB + b2]
                + red2[(2 * NTAG + j) * NB + b2] + red2[(3 * NTAG + j) * NB + b2];
        g_emit[s][b2][j] = v + bl[j];
    }
}

// ---------------- CRF forward + gold score + loss ----------------
__global__ void k_crf(const int* __restrict__ tags, const float* __restrict__ trans,
                      float* __restrict__ out) {
    int b = blockIdx.x;
    int j = threadIdx.x;
    float Tcol[NTAG];
#pragma unroll
    for (int i = 0; i < NTAG; i++) Tcol[i] = (j < NTAG) ? trans[i * NTAG + j] : 0.f;
    float dcur = (j < NTAG) ? g_emit[0][b][j] : -1e30f;

    float ts = 0.f;
    for (int s = j; s < SEQ; s += 32) {
        int tg = tags[b * SEQ + s];
        ts += g_emit[s][b][tg];
        if (s < SEQ - 1) ts += trans[tg * NTAG + tags[b * SEQ + s + 1]];
    }
#pragma unroll
    for (int off = 16; off; off >>= 1) ts += __shfl_xor_sync(0xffffffffu, ts, off);

    for (int s = 1; s < SEQ; s++) {
        float v[NTAG];
#pragma unroll
        for (int i = 0; i < NTAG; i++)
            v[i] = __shfl_sync(0xffffffffu, dcur, i) + Tcol[i];
        float mx = v[0];
#pragma unroll
        for (int i = 1; i < NTAG; i++) mx = fmaxf(mx, v[i]);
        float sum = 0.f;
#pragma unroll
        for (int i = 0; i < NTAG; i++) sum += expf(v[i] - mx);
        float e = (j < NTAG) ? g_emit[s][b][j] : 0.f;
        dcur = e + mx + logf(sum);
    }

    float dd = (j < NTAG) ? dcur : -1e30f;
    float mm = dd;
#pragma unroll
    for (int off = 16; off; off >>= 1) mm = fmaxf(mm, __shfl_xor_sync(0xffffffffu, mm, off));
    float se = (j < NTAG) ? expf(dd - mm) : 0.f;
#pragma unroll
    for (int off = 16; off; off >>= 1) se += __shfl_xor_sync(0xffffffffu, se, off);
    if (j == 0) out[b] = mm + logf(se) - ts;
}

// ---------------- launch ----------------
extern "C" void kernel_launch(void* const* d_in, const int* in_sizes, int n_in,
                              void* d_out, int out_size) {
    const int*   sentences = (const int*)d_in[0];
    const int*   tags      = (const int*)d_in[1];
    const float* emb       = (const float*)d_in[2];
    const float* W_ih_f    = (const float*)d_in[3];
    const float* W_hh_f    = (const float*)d_in[4];
    const float* b_f       = (const float*)d_in[5];
    const float* W_ih_b    = (const float*)d_in[6];
    const float* W_hh_b    = (const float*)d_in[7];
    const float* b_b       = (const float*)d_in[8];
    const float* W_lin     = (const float*)d_in[9];
    const float* b_lin     = (const float*)d_in[10];
    const float* trans     = (const float*)d_in[11];
    float* out = (float*)d_out;

    int smem_ip = (HID * IP_ROWS + 4 * IP_CHF) * 4;                     // 102720 B
    int smem_rc = (HID * 152 + HID * RBS) * 4 + R_KS * R_ACT * 8;       // 230912 B
    cudaFuncSetAttribute(k_inproj, cudaFuncAttributeMaxDynamicSharedMemorySize, smem_ip);
    cudaFuncSetAttribute(k_recur,  cudaFuncAttributeMaxDynamicSharedMemorySize, smem_rc);

    k_reset<<<1, 32>>>();
    k_gather<<<SEQ, 256>>>(sentences, emb);
    dim3 gip(IP_JS, IP_MB, 2);
    k_inproj<<<gip, IP_THREADS, smem_ip>>>(W_ih_f, b_f, W_ih_b, b_b);
    k_recur<<<2 * RBG * RUS, R_THREADS, smem_rc>>>(W_hh_f, W_hh_b);
    k_emit<<<SEQ, 256>>>(W_lin, b_lin);
    k_crf<<<NB, 32>>>(tags, trans, out);
}